// round 2
// baseline (speedup 1.0000x reference)
#include <cuda_runtime.h>
#include <math.h>

#define NB   4
#define SEQ  2048
#define DIMM 2048
#define LATD 512
#define KVDD 128
#define NHH  16
#define NKVV 4
#define HDD  32

// ---------------- scratch (device globals; no allocations allowed) ----------------
__device__ float g_qpre[NB*SEQ*LATD];     // q after proj+rms  [B,S,512]
__device__ float g_kpre[NB*SEQ*KVDD];     // k after proj+rms  [B,S,128]
__device__ float g_vbuf[NB*SEQ*KVDD];     // v after proj+rms  [B,S,128]
__device__ float g_qf  [NB*NHH*SEQ*HDD];  // final q [B,16,S,32]
__device__ float g_kf  [NB*NKVV*SEQ*HDD]; // final k [B,4,S,32]
__device__ float g_vf  [NB*NKVV*SEQ*HDD]; // final v [B,4,S,32]
__device__ float g_attn[NB*SEQ*LATD];     // attention out [B,S,512]

// ---------------- generic SGEMM: C[M,N] = A[M,K] @ B[N,K]^T (fp32) ----------------
// BM=BN=128, BK=8, 256 threads, 8x8 per thread. M%128==0, N%128==0, K%8==0 required.
__global__ __launch_bounds__(256) void sgemm_nt(
    const float* __restrict__ A, const float* __restrict__ B, float* __restrict__ C,
    int M, int N, int K)
{
    __shared__ float As[8][128];
    __shared__ float Bs[8][128];
    const int tid  = threadIdx.x;
    const int brow = blockIdx.y * 128;
    const int bcol = blockIdx.x * 128;
    const int lr = tid >> 1;
    const int lc = (tid & 1) * 4;
    const int ty = tid >> 4;
    const int tx = tid & 15;
    const float* Ap = A + (size_t)(brow + lr) * K + lc;
    const float* Bp = B + (size_t)(bcol + lr) * K + lc;

    float acc[8][8];
    #pragma unroll
    for (int i = 0; i < 8; i++)
        #pragma unroll
        for (int j = 0; j < 8; j++) acc[i][j] = 0.f;

    for (int k0 = 0; k0 < K; k0 += 8) {
        float4 av = *(const float4*)(Ap + k0);
        float4 bv = *(const float4*)(Bp + k0);
        As[lc+0][lr] = av.x; As[lc+1][lr] = av.y; As[lc+2][lr] = av.z; As[lc+3][lr] = av.w;
        Bs[lc+0][lr] = bv.x; Bs[lc+1][lr] = bv.y; Bs[lc+2][lr] = bv.z; Bs[lc+3][lr] = bv.w;
        __syncthreads();
        #pragma unroll
        for (int kk = 0; kk < 8; kk++) {
            float ra[8], rb[8];
            #pragma unroll
            for (int i = 0; i < 8; i++) ra[i] = As[kk][ty*8 + i];
            #pragma unroll
            for (int j = 0; j < 8; j++) rb[j] = Bs[kk][tx*8 + j];
            #pragma unroll
            for (int i = 0; i < 8; i++)
                #pragma unroll
                for (int j = 0; j < 8; j++) acc[i][j] = fmaf(ra[i], rb[j], acc[i][j]);
        }
        __syncthreads();
    }
    #pragma unroll
    for (int i = 0; i < 8; i++) {
        float* Cp = C + (size_t)(brow + ty*8 + i) * N + bcol + tx*8;
        #pragma unroll
        for (int j = 0; j < 8; j += 4) {
            float4 v = make_float4(acc[i][j], acc[i][j+1], acc[i][j+2], acc[i][j+3]);
            *(float4*)(Cp + j) = v;
        }
    }
}

// ---------------- in-place RMS norm over last dim ----------------
__global__ __launch_bounds__(128) void rms_kernel(
    float* __restrict__ buf, const float* __restrict__ g, int C)
{
    size_t row = blockIdx.x;
    float* p = buf + row * C;
    float ss = 0.f;
    for (int i = threadIdx.x; i < C; i += 128) { float v = p[i]; ss = fmaf(v, v, ss); }
    __shared__ float red[4];
    #pragma unroll
    for (int o = 16; o; o >>= 1) ss += __shfl_xor_sync(0xffffffffu, ss, o);
    if ((threadIdx.x & 31) == 0) red[threadIdx.x >> 5] = ss;
    __syncthreads();
    ss = red[0] + red[1] + red[2] + red[3];
    float r = rsqrtf(ss / C + 1e-6f);
    for (int i = threadIdx.x; i < C; i += 128) p[i] = p[i] * r * g[i];
}

// ---------------- fused middle: conv + rms + cross-mix + post-rms + head-norm + rope ----------------
// one block per (b, s); 128 threads
__global__ __launch_bounds__(128) void mid_kernel(
    const float* __restrict__ qpre, const float* __restrict__ kpre, const float* __restrict__ vbuf,
    const float* __restrict__ cqw,  const float* __restrict__ ckw,
    const float* __restrict__ gconv, const float* __restrict__ gkconv,
    const float* __restrict__ gpostq, const float* __restrict__ gpostk,
    const float* __restrict__ ktemp,
    float* __restrict__ qf, float* __restrict__ kf, float* __restrict__ vf)
{
    int bs  = blockIdx.x;
    int b   = bs >> 11, s = bs & 2047;
    int tid = threadIdx.x;

    __shared__ float sq[3][512];
    __shared__ float sk[3][128];
    __shared__ float qc[512], kc[128];
    __shared__ float qm[32], km[32];
    __shared__ float red[4];
    __shared__ float sclq[16], sclk[4];
    __shared__ float s_rq, s_rk, s_r2q, s_r2k;

    // load 3 causal rows of post-rms q/k
    for (int t = 0; t < 3; t++) {
        int srow = s - 2 + t;
        if (srow >= 0) {
            const float* srcq = qpre + ((size_t)b * 2048 + srow) * 512;
            for (int i = tid; i < 512; i += 128) sq[t][i] = srcq[i];
            const float* srck = kpre + ((size_t)b * 2048 + srow) * 128;
            sk[t][tid] = srck[tid];
        } else {
            for (int i = tid; i < 512; i += 128) sq[t][i] = 0.f;
            sk[t][tid] = 0.f;
        }
    }
    __syncthreads();

    // grouped causal conv (q: 16 groups x 32ch, k: 4 groups x 32ch); w[c][i][t], t=2 is current step
    for (int c = tid; c < 512; c += 128) {
        int gb = (c >> 5) << 5;
        const float* w = cqw + c * 96;
        float a = 0.f;
        #pragma unroll
        for (int i = 0; i < 32; i++) {
            int ch = gb + i;
            a = fmaf(w[i*3+0], sq[0][ch], a);
            a = fmaf(w[i*3+1], sq[1][ch], a);
            a = fmaf(w[i*3+2], sq[2][ch], a);
        }
        qc[c] = a;
    }
    {
        int c = tid; int gb = (c >> 5) << 5;
        const float* w = ckw + c * 96;
        float a = 0.f;
        #pragma unroll
        for (int i = 0; i < 32; i++) {
            int ch = gb + i;
            a = fmaf(w[i*3+0], sk[0][ch], a);
            a = fmaf(w[i*3+1], sk[1][ch], a);
            a = fmaf(w[i*3+2], sk[2][ch], a);
        }
        kc[c] = a;
    }
    // head means of the PRE-conv (post first rms) tensors, current row only
    if (tid < 32) {
        float a = 0.f;
        #pragma unroll
        for (int h = 0; h < 16; h++) a += sq[2][h*32 + tid];
        qm[tid] = a * (1.0f/16.0f);
        float bb = 0.f;
        #pragma unroll
        for (int g2 = 0; g2 < 4; g2++) bb += sk[2][g2*32 + tid];
        km[tid] = bb * 0.25f;
    }
    __syncthreads();

    // rms over conv outputs
    float pq = 0.f;
    for (int i = tid; i < 512; i += 128) pq = fmaf(qc[i], qc[i], pq);
    float pk = kc[tid] * kc[tid];
    #pragma unroll
    for (int o = 16; o; o >>= 1) pq += __shfl_xor_sync(0xffffffffu, pq, o);
    if ((tid & 31) == 0) red[tid >> 5] = pq;
    __syncthreads();
    if (tid == 0) s_rq = rsqrtf((red[0]+red[1]+red[2]+red[3]) * (1.f/512.f) + 1e-6f);
    __syncthreads();
    #pragma unroll
    for (int o = 16; o; o >>= 1) pk += __shfl_xor_sync(0xffffffffu, pk, o);
    if ((tid & 31) == 0) red[tid >> 5] = pk;
    __syncthreads();
    if (tid == 0) s_rk = rsqrtf((red[0]+red[1]+red[2]+red[3]) * (1.f/128.f) + 1e-6f);
    __syncthreads();
    float rq = s_rq, rk = s_rk;

    // apply rms gains + cross-mix (GAIN=0.25)
    for (int i = tid; i < 512; i += 128) qc[i] = qc[i] * rq * gconv[i]  + 0.25f * km[i & 31];
    kc[tid] = kc[tid] * rk * gkconv[tid] + 0.25f * qm[tid & 31];
    __syncthreads();

    // post-rms
    float p2q = 0.f;
    for (int i = tid; i < 512; i += 128) p2q = fmaf(qc[i], qc[i], p2q);
    float p2k = kc[tid] * kc[tid];
    #pragma unroll
    for (int o = 16; o; o >>= 1) p2q += __shfl_xor_sync(0xffffffffu, p2q, o);
    if ((tid & 31) == 0) red[tid >> 5] = p2q;
    __syncthreads();
    if (tid == 0) s_r2q = rsqrtf((red[0]+red[1]+red[2]+red[3]) * (1.f/512.f) + 1e-6f);
    __syncthreads();
    #pragma unroll
    for (int o = 16; o; o >>= 1) p2k += __shfl_xor_sync(0xffffffffu, p2k, o);
    if ((tid & 31) == 0) red[tid >> 5] = p2k;
    __syncthreads();
    if (tid == 0) s_r2k = rsqrtf((red[0]+red[1]+red[2]+red[3]) * (1.f/128.f) + 1e-6f);
    __syncthreads();
    float r2q = s_r2q, r2k = s_r2k;
    for (int i = tid; i < 512; i += 128) qc[i] = qc[i] * r2q * gpostq[i];
    kc[tid] = kc[tid] * r2k * gpostk[tid];
    __syncthreads();

    // per-head L2 norm -> scale to sqrt(HD) (k also * key_temp)
    if (tid < 16) {
        float a = 0.f;
        #pragma unroll
        for (int d = 0; d < 32; d++) { float v = qc[tid*32 + d]; a = fmaf(v, v, a); }
        sclq[tid] = 5.656854249492381f / fmaxf(sqrtf(a), 1e-12f);
    }
    if (tid >= 16 && tid < 20) {
        int g2 = tid - 16; float a = 0.f;
        #pragma unroll
        for (int d = 0; d < 32; d++) { float v = kc[g2*32 + d]; a = fmaf(v, v, a); }
        sclk[g2] = 5.656854249492381f * ktemp[0] / fmaxf(sqrtf(a), 1e-12f);
    }
    __syncthreads();

    // rope (interleaved pairs) + write to [B,H,S,32]
    for (int p = tid; p < 256; p += 128) {
        int h = p >> 4, d2 = p & 15;
        float fr = powf(10000.f, -(float)d2 * (1.f/16.f));
        float ang = (float)s * fr;
        float sn, cs; sincosf(ang, &sn, &cs);
        float scl = sclq[h];
        float x0 = qc[h*32 + 2*d2]     * scl;
        float x1 = qc[h*32 + 2*d2 + 1] * scl;
        float* dst = qf + (((size_t)(b*16 + h)) * 2048 + s) * 32 + 2*d2;
        dst[0] = x0*cs - x1*sn;
        dst[1] = x0*sn + x1*cs;
    }
    if (tid < 64) {
        int g2 = tid >> 4, d2 = tid & 15;
        float fr = powf(10000.f, -(float)d2 * (1.f/16.f));
        float ang = (float)s * fr;
        float sn, cs; sincosf(ang, &sn, &cs);
        float scl = sclk[g2];
        float x0 = kc[g2*32 + 2*d2]     * scl;
        float x1 = kc[g2*32 + 2*d2 + 1] * scl;
        float* dst = kf + (((size_t)(b*4 + g2)) * 2048 + s) * 32 + 2*d2;
        dst[0] = x0*cs - x1*sn;
        dst[1] = x0*sn + x1*cs;
    }
    // v: relayout to [B,4,S,32]
    {
        const float* vr = vbuf + ((size_t)b * 2048 + s) * 128;
        float vv = vr[tid];
        int g2 = tid >> 5, d = tid & 31;
        vf[(((size_t)(b*4 + g2)) * 2048 + s) * 32 + d] = vv;
    }
}

// ---------------- fp32 flash attention (causal, GQA) ----------------
// grid (B*NH, S/64), 128 threads; thread pair (r, half) handles one query row,
// each half owns 32 key columns. q kept in registers; K/V smem reads are broadcasts.
__global__ __launch_bounds__(128) void attn_kernel(
    const float* __restrict__ qf, const float* __restrict__ kf, const float* __restrict__ vf,
    float* __restrict__ attn)
{
    int bh  = blockIdx.x;            // b*16 + h
    int qt  = blockIdx.y;
    int b   = bh >> 4, h = bh & 15;
    int kvh = h >> 2;
    int tid = threadIdx.x;
    int r = tid >> 1, half = tid & 1;
    int qrow = qt * 64 + r;

    __shared__ float Kt[64][32];
    __shared__ float Vt[64][32];

    const float scale = 0.17677669529663687f;  // 1/sqrt(32)
    float qreg[32];
    const float* qp = qf + (((size_t)bh) * 2048 + qrow) * 32;
    #pragma unroll
    for (int d = 0; d < 32; d++) qreg[d] = qp[d] * scale;

    float m = -3.0e38f, l = 0.f;
    float acc[32];
    #pragma unroll
    for (int d = 0; d < 32; d++) acc[d] = 0.f;

    const float* kbase = kf + ((size_t)(b*4 + kvh)) * 2048 * 32;
    const float* vbase = vf + ((size_t)(b*4 + kvh)) * 2048 * 32;

    for (int j = 0; j <= qt; j++) {
        int c0 = j * 64;
        for (int idx = tid; idx < 64*32; idx += 128) {
            Kt[idx >> 5][idx & 31] = kbase[(size_t)c0 * 32 + idx];
            Vt[idx >> 5][idx & 31] = vbase[(size_t)c0 * 32 + idx];
        }
        __syncthreads();

        float sc[32];
        float mloc = -3.0e38f;
        #pragma unroll
        for (int j2 = 0; j2 < 32; j2++) {
            int c = half*32 + j2;
            float a = 0.f;
            #pragma unroll
            for (int d = 0; d < 32; d++) a = fmaf(qreg[d], Kt[c][d], a);
            if (j == qt && (c0 + c) > qrow) a = -3.0e38f;
            sc[j2] = a;
            mloc = fmaxf(mloc, a);
        }
        mloc = fmaxf(mloc, __shfl_xor_sync(0xffffffffu, mloc, 1));
        float mnew  = fmaxf(m, mloc);
        float alpha = __expf(m - mnew);
        float lloc  = 0.f;
        #pragma unroll
        for (int j2 = 0; j2 < 32; j2++) {
            float pp = __expf(sc[j2] - mnew);
            sc[j2] = pp;
            lloc += pp;
        }
        lloc += __shfl_xor_sync(0xffffffffu, lloc, 1);
        l = l * alpha + lloc;
        m = mnew;
        #pragma unroll
        for (int d = 0; d < 32; d++) acc[d] *= alpha;
        #pragma unroll
        for (int j2 = 0; j2 < 32; j2++) {
            float pp = sc[j2];
            const float* vrow = Vt[half*32 + j2];
            #pragma unroll
            for (int d = 0; d < 32; d++) acc[d] = fmaf(pp, vrow[d], acc[d]);
        }
        __syncthreads();
    }

    float invl = 1.f / l;
    #pragma unroll
    for (int d = 0; d < 32; d++) acc[d] += __shfl_xor_sync(0xffffffffu, acc[d], 1);
    if (half == 0) {
        float* op = attn + (((size_t)b * 2048) + qrow) * 512 + h*32;
        #pragma unroll
        for (int d = 0; d < 32; d++) op[d] = acc[d] * invl;
    }
}

// ---------------- launcher ----------------
extern "C" void kernel_launch(void* const* d_in, const int* in_sizes, int n_in,
                              void* d_out, int out_size)
{
    const float* x       = (const float*)d_in[0];
    const float* w_q     = (const float*)d_in[1];
    const float* w_k     = (const float*)d_in[2];
    const float* w_v     = (const float*)d_in[3];
    const float* g_lat   = (const float*)d_in[4];
    const float* g_kv    = (const float*)d_in[5];
    const float* cqw     = (const float*)d_in[6];
    const float* ckw     = (const float*)d_in[7];
    const float* gconv   = (const float*)d_in[8];
    const float* gkconv  = (const float*)d_in[9];
    const float* gpostq  = (const float*)d_in[10];
    const float* gpostk  = (const float*)d_in[11];
    const float* ktemp   = (const float*)d_in[12];
    const float* gpreout = (const float*)d_in[13];
    const float* w_o     = (const float*)d_in[14];
    float* out = (float*)d_out;

    float *qpre, *kpre, *vbuf, *qf, *kf, *vf, *attn;
    cudaGetSymbolAddress((void**)&qpre, g_qpre);
    cudaGetSymbolAddress((void**)&kpre, g_kpre);
    cudaGetSymbolAddress((void**)&vbuf, g_vbuf);
    cudaGetSymbolAddress((void**)&qf,   g_qf);
    cudaGetSymbolAddress((void**)&kf,   g_kf);
    cudaGetSymbolAddress((void**)&vf,   g_vf);
    cudaGetSymbolAddress((void**)&attn, g_attn);

    const int M = NB * SEQ;  // 8192

    // QKV projections
    sgemm_nt<<<dim3(LATD/128, M/128), 256>>>(x, w_q, qpre, M, LATD, DIMM);
    sgemm_nt<<<dim3(KVDD/128, M/128), 256>>>(x, w_k, kpre, M, KVDD, DIMM);
    sgemm_nt<<<dim3(KVDD/128, M/128), 256>>>(x, w_v, vbuf, M, KVDD, DIMM);

    // first RMS norms
    rms_kernel<<<M, 128>>>(qpre, g_lat, LATD);
    rms_kernel<<<M, 128>>>(kpre, g_kv,  KVDD);
    rms_kernel<<<M, 128>>>(vbuf, g_kv,  KVDD);

    // fused conv / mix / post-rms / head-norm / rope / relayout
    mid_kernel<<<M, 128>>>(qpre, kpre, vbuf, cqw, ckw, gconv, gkconv,
                           gpostq, gpostk, ktemp, qf, kf, vf);

    // causal GQA attention
    attn_kernel<<<dim3(NB*NHH, SEQ/64), 128>>>(qf, kf, vf, attn);

    // pre-output RMS + output projection
    rms_kernel<<<M, 128>>>(attn, gpreout, LATD);
    sgemm_nt<<<dim3(DIMM/128, M/128), 256>>>(attn, w_o, out, M, DIMM, LATD);
}

// round 5
// speedup vs baseline: 1.3681x; 1.3681x over previous
#include <cuda_runtime.h>
#include <math.h>

#define NB   4
#define SEQ  2048
#define DIMM 2048
#define LATD 512
#define KVDD 128
#define NHH  16
#define NKVV 4
#define HDD  32

typedef unsigned long long u64;

// ---------------- scratch (device globals; no allocations allowed) ----------------
__device__ float g_qpre[NB*SEQ*LATD];     // q after proj+rms  [B,S,512]
__device__ float g_kpre[NB*SEQ*KVDD];     // k after proj+rms  [B,S,128]
__device__ float g_vbuf[NB*SEQ*KVDD];     // v after proj+rms  [B,S,128]
__device__ float g_qf  [NB*NHH*SEQ*HDD];  // final q [B,16,S,32]
__device__ float g_kf  [NB*NKVV*SEQ*HDD]; // final k [B,4,S,32]
__device__ float g_vf  [NB*NKVV*SEQ*HDD]; // final v [B,4,S,32]
__device__ float g_attn[NB*SEQ*LATD];     // attention out [B,S,512]

// ---------------- packed f32x2 helpers ----------------
__device__ __forceinline__ u64 ffma2(u64 a, u64 b, u64 c) {
    u64 d; asm("fma.rn.f32x2 %0,%1,%2,%3;" : "=l"(d) : "l"(a), "l"(b), "l"(c)); return d;
}
__device__ __forceinline__ u64 fmul2(u64 a, u64 b) {
    u64 d; asm("mul.rn.f32x2 %0,%1,%2;" : "=l"(d) : "l"(a), "l"(b)); return d;
}
__device__ __forceinline__ u64 fadd2(u64 a, u64 b) {
    u64 d; asm("add.rn.f32x2 %0,%1,%2;" : "=l"(d) : "l"(a), "l"(b)); return d;
}
__device__ __forceinline__ u64 pack2(float lo, float hi) {
    u64 d; asm("mov.b64 %0,{%1,%2};" : "=l"(d) : "f"(lo), "f"(hi)); return d;
}
__device__ __forceinline__ void unpack2(u64 v, float& lo, float& hi) {
    asm("mov.b64 {%0,%1},%2;" : "=f"(lo), "=f"(hi) : "l"(v));
}
__device__ __forceinline__ float f2tf32f(float f) {
    unsigned u; asm("cvt.rna.tf32.f32 %0, %1;" : "=r"(u) : "f"(f));
    return __uint_as_float(u);
}

// ---------------- tf32 tensor-core GEMM: C[M,N] = A[M,K] @ B[N,K]^T ----------------
// BM=BN=128, BK=16, 256 threads = 8 warps (2 x 4), warp tile 64x32, mma m16n8k8.
// Requires M%128==0, N%128==0, K%16==0.
__device__ __forceinline__ void mma_tf32(float* c, const unsigned* a, const unsigned* b) {
    asm volatile(
        "mma.sync.aligned.m16n8k8.row.col.f32.tf32.tf32.f32 "
        "{%0,%1,%2,%3},{%4,%5,%6,%7},{%8,%9},{%0,%1,%2,%3};"
        : "+f"(c[0]), "+f"(c[1]), "+f"(c[2]), "+f"(c[3])
        : "r"(a[0]), "r"(a[1]), "r"(a[2]), "r"(a[3]), "r"(b[0]), "r"(b[1]));
}

__global__ __launch_bounds__(256) void gemm_tf32(
    const float* __restrict__ A, const float* __restrict__ B, float* __restrict__ C,
    int M, int N, int K)
{
    __shared__ float As[16][136];   // [k][m], stride 136 -> conflict-free frag loads
    __shared__ float Bs[16][136];   // [k][n]

    const int tid  = threadIdx.x;
    const int warp = tid >> 5, lane = tid & 31;
    const int g = lane >> 2, tg = lane & 3;
    const int wm = (warp >> 2) * 64;      // 0 or 64
    const int wn = (warp & 3) * 32;      // 0,32,64,96
    const int brow = blockIdx.y * 128;
    const int bcol = blockIdx.x * 128;

    const int lrow = tid >> 1;            // 0..127
    const int kq   = (tid & 1) * 8;       // 0 or 8
    const float* Ag = A + (size_t)(brow + lrow) * K + kq;
    const float* Bg = B + (size_t)(bcol + lrow) * K + kq;

    float acc[4][4][4];
    #pragma unroll
    for (int i = 0; i < 4; i++)
        #pragma unroll
        for (int j = 0; j < 4; j++)
            #pragma unroll
            for (int t = 0; t < 4; t++) acc[i][j][t] = 0.f;

    for (int k0 = 0; k0 < K; k0 += 16) {
        float4 a0 = *(const float4*)(Ag + k0);
        float4 a1 = *(const float4*)(Ag + k0 + 4);
        float4 b0 = *(const float4*)(Bg + k0);
        float4 b1 = *(const float4*)(Bg + k0 + 4);
        __syncthreads();
        As[kq+0][lrow] = f2tf32f(a0.x); As[kq+1][lrow] = f2tf32f(a0.y);
        As[kq+2][lrow] = f2tf32f(a0.z); As[kq+3][lrow] = f2tf32f(a0.w);
        As[kq+4][lrow] = f2tf32f(a1.x); As[kq+5][lrow] = f2tf32f(a1.y);
        As[kq+6][lrow] = f2tf32f(a1.z); As[kq+7][lrow] = f2tf32f(a1.w);
        Bs[kq+0][lrow] = f2tf32f(b0.x); Bs[kq+1][lrow] = f2tf32f(b0.y);
        Bs[kq+2][lrow] = f2tf32f(b0.z); Bs[kq+3][lrow] = f2tf32f(b0.w);
        Bs[kq+4][lrow] = f2tf32f(b1.x); Bs[kq+5][lrow] = f2tf32f(b1.y);
        Bs[kq+6][lrow] = f2tf32f(b1.z); Bs[kq+7][lrow] = f2tf32f(b1.w);
        __syncthreads();

        #pragma unroll
        for (int ks = 0; ks < 2; ks++) {
            const int kb = ks * 8;
            unsigned af[4][4], bf[4][2];
            #pragma unroll
            for (int mf = 0; mf < 4; mf++) {
                int r0 = wm + mf*16 + g;
                af[mf][0] = __float_as_uint(As[kb+tg  ][r0  ]);
                af[mf][1] = __float_as_uint(As[kb+tg  ][r0+8]);
                af[mf][2] = __float_as_uint(As[kb+tg+4][r0  ]);
                af[mf][3] = __float_as_uint(As[kb+tg+4][r0+8]);
            }
            #pragma unroll
            for (int nf = 0; nf < 4; nf++) {
                int cn = wn + nf*8 + g;
                bf[nf][0] = __float_as_uint(Bs[kb+tg  ][cn]);
                bf[nf][1] = __float_as_uint(Bs[kb+tg+4][cn]);
            }
            #pragma unroll
            for (int mf = 0; mf < 4; mf++)
                #pragma unroll
                for (int nf = 0; nf < 4; nf++)
                    mma_tf32(acc[mf][nf], af[mf], bf[nf]);
        }
    }

    #pragma unroll
    for (int mf = 0; mf < 4; mf++) {
        int r = brow + wm + mf*16 + g;
        #pragma unroll
        for (int nf = 0; nf < 4; nf++) {
            int cn = bcol + wn + nf*8 + tg*2;
            *(float2*)(C + (size_t)r * N + cn)       = make_float2(acc[mf][nf][0], acc[mf][nf][1]);
            *(float2*)(C + (size_t)(r+8) * N + cn)   = make_float2(acc[mf][nf][2], acc[mf][nf][3]);
        }
    }
}

// ---------------- in-place RMS norm over last dim ----------------
__global__ __launch_bounds__(128) void rms_kernel(
    float* __restrict__ buf, const float* __restrict__ g, int C)
{
    size_t row = blockIdx.x;
    float* p = buf + row * C;
    float ss = 0.f;
    for (int i = threadIdx.x; i < C; i += 128) { float v = p[i]; ss = fmaf(v, v, ss); }
    __shared__ float red[4];
    #pragma unroll
    for (int o = 16; o; o >>= 1) ss += __shfl_xor_sync(0xffffffffu, ss, o);
    if ((threadIdx.x & 31) == 0) red[threadIdx.x >> 5] = ss;
    __syncthreads();
    ss = red[0] + red[1] + red[2] + red[3];
    float r = rsqrtf(ss / C + 1e-6f);
    for (int i = threadIdx.x; i < C; i += 128) p[i] = p[i] * r * g[i];
}

// ---------------- fused middle: conv + rms + cross-mix + post-rms + head-norm + rope ----------------
__global__ __launch_bounds__(128) void mid_kernel(
    const float* __restrict__ qpre, const float* __restrict__ kpre, const float* __restrict__ vbuf,
    const float* __restrict__ cqw,  const float* __restrict__ ckw,
    const float* __restrict__ gconv, const float* __restrict__ gkconv,
    const float* __restrict__ gpostq, const float* __restrict__ gpostk,
    const float* __restrict__ ktemp,
    float* __restrict__ qf, float* __restrict__ kf, float* __restrict__ vf)
{
    int bs  = blockIdx.x;
    int b   = bs >> 11, s = bs & 2047;
    int tid = threadIdx.x;

    __shared__ float sq[3][512];
    __shared__ float sk[3][128];
    __shared__ float qc[512], kc[128];
    __shared__ float qm[32], km[32];
    __shared__ float red[4];
    __shared__ float sclq[16], sclk[4];
    __shared__ float s_rq, s_rk, s_r2q, s_r2k;

    for (int t = 0; t < 3; t++) {
        int srow = s - 2 + t;
        if (srow >= 0) {
            const float* srcq = qpre + ((size_t)b * 2048 + srow) * 512;
            for (int i = tid; i < 512; i += 128) sq[t][i] = srcq[i];
            const float* srck = kpre + ((size_t)b * 2048 + srow) * 128;
            sk[t][tid] = srck[tid];
        } else {
            for (int i = tid; i < 512; i += 128) sq[t][i] = 0.f;
            sk[t][tid] = 0.f;
        }
    }
    __syncthreads();

    for (int c = tid; c < 512; c += 128) {
        int gb = (c >> 5) << 5;
        const float* w = cqw + c * 96;
        float a = 0.f;
        #pragma unroll
        for (int i = 0; i < 32; i++) {
            int ch = gb + i;
            a = fmaf(w[i*3+0], sq[0][ch], a);
            a = fmaf(w[i*3+1], sq[1][ch], a);
            a = fmaf(w[i*3+2], sq[2][ch], a);
        }
        qc[c] = a;
    }
    {
        int c = tid; int gb = (c >> 5) << 5;
        const float* w = ckw + c * 96;
        float a = 0.f;
        #pragma unroll
        for (int i = 0; i < 32; i++) {
            int ch = gb + i;
            a = fmaf(w[i*3+0], sk[0][ch], a);
            a = fmaf(w[i*3+1], sk[1][ch], a);
            a = fmaf(w[i*3+2], sk[2][ch], a);
        }
        kc[c] = a;
    }
    if (tid < 32) {
        float a = 0.f;
        #pragma unroll
        for (int h = 0; h < 16; h++) a += sq[2][h*32 + tid];
        qm[tid] = a * (1.0f/16.0f);
        float bb = 0.f;
        #pragma unroll
        for (int g2 = 0; g2 < 4; g2++) bb += sk[2][g2*32 + tid];
        km[tid] = bb * 0.25f;
    }
    __syncthreads();

    float pq = 0.f;
    for (int i = tid; i < 512; i += 128) pq = fmaf(qc[i], qc[i], pq);
    float pk = kc[tid] * kc[tid];
    #pragma unroll
    for (int o = 16; o; o >>= 1) pq += __shfl_xor_sync(0xffffffffu, pq, o);
    if ((tid & 31) == 0) red[tid >> 5] = pq;
    __syncthreads();
    if (tid == 0) s_rq = rsqrtf((red[0]+red[1]+red[2]+red[3]) * (1.f/512.f) + 1e-6f);
    __syncthreads();
    #pragma unroll
    for (int o = 16; o; o >>= 1) pk += __shfl_xor_sync(0xffffffffu, pk, o);
    if ((tid & 31) == 0) red[tid >> 5] = pk;
    __syncthreads();
    if (tid == 0) s_rk = rsqrtf((red[0]+red[1]+red[2]+red[3]) * (1.f/128.f) + 1e-6f);
    __syncthreads();
    float rq = s_rq, rk = s_rk;

    for (int i = tid; i < 512; i += 128) qc[i] = qc[i] * rq * gconv[i]  + 0.25f * km[i & 31];
    kc[tid] = kc[tid] * rk * gkconv[tid] + 0.25f * qm[tid & 31];
    __syncthreads();

    float p2q = 0.f;
    for (int i = tid; i < 512; i += 128) p2q = fmaf(qc[i], qc[i], p2q);
    float p2k = kc[tid] * kc[tid];
    #pragma unroll
    for (int o = 16; o; o >>= 1) p2q += __shfl_xor_sync(0xffffffffu, p2q, o);
    if ((tid & 31) == 0) red[tid >> 5] = p2q;
    __syncthreads();
    if (tid == 0) s_r2q = rsqrtf((red[0]+red[1]+red[2]+red[3]) * (1.f/512.f) + 1e-6f);
    __syncthreads();
    #pragma unroll
    for (int o = 16; o; o >>= 1) p2k += __shfl_xor_sync(0xffffffffu, p2k, o);
    if ((tid & 31) == 0) red[tid >> 5] = p2k;
    __syncthreads();
    if (tid == 0) s_r2k = rsqrtf((red[0]+red[1]+red[2]+red[3]) * (1.f/128.f) + 1e-6f);
    __syncthreads();
    float r2q = s_r2q, r2k = s_r2k;
    for (int i = tid; i < 512; i += 128) qc[i] = qc[i] * r2q * gpostq[i];
    kc[tid] = kc[tid] * r2k * gpostk[tid];
    __syncthreads();

    if (tid < 16) {
        float a = 0.f;
        #pragma unroll
        for (int d = 0; d < 32; d++) { float v = qc[tid*32 + d]; a = fmaf(v, v, a); }
        sclq[tid] = 5.656854249492381f / fmaxf(sqrtf(a), 1e-12f);
    }
    if (tid >= 16 && tid < 20) {
        int g2 = tid - 16; float a = 0.f;
        #pragma unroll
        for (int d = 0; d < 32; d++) { float v = kc[g2*32 + d]; a = fmaf(v, v, a); }
        sclk[g2] = 5.656854249492381f * ktemp[0] / fmaxf(sqrtf(a), 1e-12f);
    }
    __syncthreads();

    for (int p = tid; p < 256; p += 128) {
        int h = p >> 4, d2 = p & 15;
        float fr = powf(10000.f, -(float)d2 * (1.f/16.f));
        float ang = (float)s * fr;
        float sn, cs; sincosf(ang, &sn, &cs);
        float scl = sclq[h];
        float x0 = qc[h*32 + 2*d2]     * scl;
        float x1 = qc[h*32 + 2*d2 + 1] * scl;
        float* dst = qf + (((size_t)(b*16 + h)) * 2048 + s) * 32 + 2*d2;
        dst[0] = x0*cs - x1*sn;
        dst[1] = x0*sn + x1*cs;
    }
    if (tid < 64) {
        int g2 = tid >> 4, d2 = tid & 15;
        float fr = powf(10000.f, -(float)d2 * (1.f/16.f));
        float ang = (float)s * fr;
        float sn, cs; sincosf(ang, &sn, &cs);
        float scl = sclk[g2];
        float x0 = kc[g2*32 + 2*d2]     * scl;
        float x1 = kc[g2*32 + 2*d2 + 1] * scl;
        float* dst = kf + (((size_t)(b*4 + g2)) * 2048 + s) * 32 + 2*d2;
        dst[0] = x0*cs - x1*sn;
        dst[1] = x0*sn + x1*cs;
    }
    {
        const float* vr = vbuf + ((size_t)b * 2048 + s) * 128;
        float vv = vr[tid];
        int g2 = tid >> 5, d = tid & 31;
        vf[(((size_t)(b*4 + g2)) * 2048 + s) * 32 + d] = vv;
    }
}

// ---------------- fp32 flash attention with packed f32x2 math ----------------
// grid (B*NH, S/64), 128 threads; thread pair (r, half) handles one query row,
// each half owns 32 key columns.
__global__ __launch_bounds__(128) void attn_kernel(
    const float* __restrict__ qf, const float* __restrict__ kf, const float* __restrict__ vf,
    float* __restrict__ attn)
{
    int bh  = blockIdx.x;            // b*16 + h
    int qt  = blockIdx.y;
    int b   = bh >> 4, h = bh & 15;
    int kvh = h >> 2;
    int tid = threadIdx.x;
    int r = tid >> 1, half = tid & 1;
    int qrow = qt * 64 + r;

    __shared__ __align__(16) float Kt[64][32];
    __shared__ __align__(16) float Vt[64][32];

    const float scale = 0.17677669529663687f;  // 1/sqrt(32)
    u64 q2[16];
    {
        const float4* qp4 = (const float4*)(qf + (((size_t)bh) * 2048 + qrow) * 32);
        #pragma unroll
        for (int i = 0; i < 8; i++) {
            float4 v = qp4[i];
            q2[2*i]   = pack2(v.x * scale, v.y * scale);
            q2[2*i+1] = pack2(v.z * scale, v.w * scale);
        }
    }

    float m = -3.0e38f, l = 0.f;
    u64 acc2[16];
    #pragma unroll
    for (int i = 0; i < 16; i++) acc2[i] = 0ull;

    const float* kbase = kf + ((size_t)(b*4 + kvh)) * 2048 * 32;
    const float* vbase = vf + ((size_t)(b*4 + kvh)) * 2048 * 32;

    for (int j = 0; j <= qt; j++) {
        int c0 = j * 64;
        {
            float4* Ks = (float4*)Kt;
            float4* Vs = (float4*)Vt;
            const float4* kg = (const float4*)(kbase + (size_t)c0 * 32);
            const float4* vg = (const float4*)(vbase + (size_t)c0 * 32);
            for (int idx = tid; idx < 512; idx += 128) {
                Ks[idx] = kg[idx];
                Vs[idx] = vg[idx];
            }
        }
        __syncthreads();

        float sc[32];
        float mloc = -3.0e38f;
        #pragma unroll
        for (int j2 = 0; j2 < 32; j2++) {
            const ulonglong2* k4 = (const ulonglong2*)Kt[half*32 + j2];
            u64 s0 = 0ull, s1 = 0ull;
            #pragma unroll
            for (int dd = 0; dd < 8; dd++) {
                ulonglong2 kk = k4[dd];
                s0 = ffma2(q2[2*dd],   kk.x, s0);
                s1 = ffma2(q2[2*dd+1], kk.y, s1);
            }
            s0 = fadd2(s0, s1);
            float lo, hi; unpack2(s0, lo, hi);
            float a = lo + hi;
            if (j == qt && (c0 + half*32 + j2) > qrow) a = -3.0e38f;
            sc[j2] = a;
            mloc = fmaxf(mloc, a);
        }
        mloc = fmaxf(mloc, __shfl_xor_sync(0xffffffffu, mloc, 1));
        float mnew  = fmaxf(m, mloc);
        float alpha = __expf(m - mnew);
        float lloc  = 0.f;
        #pragma unroll
        for (int j2 = 0; j2 < 32; j2++) {
            float pp = __expf(sc[j2] - mnew);
            sc[j2] = pp;
            lloc += pp;
        }
        lloc += __shfl_xor_sync(0xffffffffu, lloc, 1);
        l = l * alpha + lloc;
        m = mnew;
        u64 al2 = pack2(alpha, alpha);
        #pragma unroll
        for (int i = 0; i < 16; i++) acc2[i] = fmul2(acc2[i], al2);
        #pragma unroll
        for (int j2 = 0; j2 < 32; j2++) {
            u64 p2 = pack2(sc[j2], sc[j2]);
            const ulonglong2* v4 = (const ulonglong2*)Vt[half*32 + j2];
            #pragma unroll
            for (int dd = 0; dd < 8; dd++) {
                ulonglong2 vv = v4[dd];
                acc2[2*dd]   = ffma2(p2, vv.x, acc2[2*dd]);
                acc2[2*dd+1] = ffma2(p2, vv.y, acc2[2*dd+1]);
            }
        }
        __syncthreads();
    }

    float invl = 1.f / l;
    float acc[32];
    #pragma unroll
    for (int i = 0; i < 16; i++) unpack2(acc2[i], acc[2*i], acc[2*i+1]);
    #pragma unroll
    for (int d = 0; d < 32; d++) acc[d] += __shfl_xor_sync(0xffffffffu, acc[d], 1);
    if (half == 0) {
        float* op = attn + (((size_t)b * 2048) + qrow) * 512 + h*32;
        #pragma unroll
        for (int d = 0; d < 32; d++) op[d] = acc[d] * invl;
    }
}

// ---------------- launcher ----------------
extern "C" void kernel_launch(void* const* d_in, const int* in_sizes, int n_in,
                              void* d_out, int out_size)
{
    const float* x       = (const float*)d_in[0];
    const float* w_q     = (const float*)d_in[1];
    const float* w_k     = (const float*)d_in[2];
    const float* w_v     = (const float*)d_in[3];
    const float* g_lat   = (const float*)d_in[4];
    const float* g_kv    = (const float*)d_in[5];
    const float* cqw     = (const float*)d_in[6];
    const float* ckw     = (const float*)d_in[7];
    const float* gconv   = (const float*)d_in[8];
    const float* gkconv  = (const float*)d_in[9];
    const float* gpostq  = (const float*)d_in[10];
    const float* gpostk  = (const float*)d_in[11];
    const float* ktemp   = (const float*)d_in[12];
    const float* gpreout = (const float*)d_in[13];
    const float* w_o     = (const float*)d_in[14];
    float* out = (float*)d_out;

    float *qpre, *kpre, *vbuf, *qf, *kf, *vf, *attn;
    cudaGetSymbolAddress((void**)&qpre, g_qpre);
    cudaGetSymbolAddress((void**)&kpre, g_kpre);
    cudaGetSymbolAddress((void**)&vbuf, g_vbuf);
    cudaGetSymbolAddress((void**)&qf,   g_qf);
    cudaGetSymbolAddress((void**)&kf,   g_kf);
    cudaGetSymbolAddress((void**)&vf,   g_vf);
    cudaGetSymbolAddress((void**)&attn, g_attn);

    const int M = NB * SEQ;  // 8192

    // QKV projections (tf32 tensor cores)
    gemm_tf32<<<dim3(LATD/128, M/128), 256>>>(x, w_q, qpre, M, LATD, DIMM);
    gemm_tf32<<<dim3(KVDD/128, M/128), 256>>>(x, w_k, kpre, M, KVDD, DIMM);
    gemm_tf32<<<dim3(KVDD/128, M/128), 256>>>(x, w_v, vbuf, M, KVDD, DIMM);

    // first RMS norms
    rms_kernel<<<M, 128>>>(qpre, g_lat, LATD);
    rms_kernel<<<M, 128>>>(kpre, g_kv,  KVDD);
    rms_kernel<<<M, 128>>>(vbuf, g_kv,  KVDD);

    // fused conv / mix / post-rms / head-norm / rope / relayout
    mid_kernel<<<M, 128>>>(qpre, kpre, vbuf, cqw, ckw, gconv, gkconv,
                           gpostq, gpostk, ktemp, qf, kf, vf);

    // causal GQA attention
    attn_kernel<<<dim3(NB*NHH, SEQ/64), 128>>>(qf, kf, vf, attn);

    // pre-output RMS + output projection
    rms_kernel<<<M, 128>>>(attn, gpreout, LATD);
    gemm_tf32<<<dim3(DIMM/128, M/128), 256>>>(attn, w_o, out, M, DIMM, LATD);
}

// round 7
// speedup vs baseline: 1.8354x; 1.3416x over previous
#include <cuda_runtime.h>
#include <cuda_fp16.h>
#include <math.h>

#define NB   4
#define SEQ  2048
#define DIMM 2048
#define LATD 512
#define KVDD 128
#define NHH  16
#define NKVV 4
#define HDD  32

// ---------------- scratch (device globals; no allocations allowed) ----------------
__device__ float g_qpre[NB*SEQ*LATD];     // q after proj+rms  [B,S,512]
__device__ float g_kpre[NB*SEQ*KVDD];     // k after proj+rms  [B,S,128]
__device__ float g_vbuf[NB*SEQ*KVDD];     // v after proj+rms  [B,S,128]
__device__ float g_qf  [NB*NHH*SEQ*HDD];  // final q [B,16,S,32]
__device__ float g_kf  [NB*NKVV*SEQ*HDD]; // final k [B,4,S,32]
__device__ float g_vf  [NB*NKVV*SEQ*HDD]; // final v [B,4,S,32]
__device__ float g_attn[NB*SEQ*LATD];     // attention out [B,S,512]

__device__ __forceinline__ float f2tf32f(float f) {
    unsigned u; asm("cvt.rna.tf32.f32 %0, %1;" : "=r"(u) : "f"(f));
    return __uint_as_float(u);
}
__device__ __forceinline__ unsigned f2tf32u(float f) {
    unsigned u; asm("cvt.rna.tf32.f32 %0, %1;" : "=r"(u) : "f"(f));
    return u;
}

// ---------------- mma helpers ----------------
__device__ __forceinline__ void mma_tf32(float* c, const unsigned* a, unsigned b0, unsigned b1) {
    asm volatile(
        "mma.sync.aligned.m16n8k8.row.col.f32.tf32.tf32.f32 "
        "{%0,%1,%2,%3},{%4,%5,%6,%7},{%8,%9},{%0,%1,%2,%3};"
        : "+f"(c[0]), "+f"(c[1]), "+f"(c[2]), "+f"(c[3])
        : "r"(a[0]), "r"(a[1]), "r"(a[2]), "r"(a[3]), "r"(b0), "r"(b1));
}
__device__ __forceinline__ void mma_f16(float* c, const unsigned* a, unsigned b0, unsigned b1) {
    asm volatile(
        "mma.sync.aligned.m16n8k16.row.col.f32.f16.f16.f32 "
        "{%0,%1,%2,%3},{%4,%5,%6,%7},{%8,%9},{%0,%1,%2,%3};"
        : "+f"(c[0]), "+f"(c[1]), "+f"(c[2]), "+f"(c[3])
        : "r"(a[0]), "r"(a[1]), "r"(a[2]), "r"(a[3]), "r"(b0), "r"(b1));
}

// ---------------- tf32 tensor-core GEMM: C[M,N] = A[M,K] @ B[N,K]^T ----------------
__global__ __launch_bounds__(256) void gemm_tf32(
    const float* __restrict__ A, const float* __restrict__ B, float* __restrict__ C,
    int M, int N, int K)
{
    __shared__ float As[16][136];
    __shared__ float Bs[16][136];

    const int tid  = threadIdx.x;
    const int warp = tid >> 5, lane = tid & 31;
    const int g = lane >> 2, tg = lane & 3;
    const int wm = (warp >> 2) * 64;
    const int wn = (warp & 3) * 32;
    const int brow = blockIdx.y * 128;
    const int bcol = blockIdx.x * 128;

    const int lrow = tid >> 1;
    const int kq   = (tid & 1) * 8;
    const float* Ag = A + (size_t)(brow + lrow) * K + kq;
    const float* Bg = B + (size_t)(bcol + lrow) * K + kq;

    float acc[4][4][4];
    #pragma unroll
    for (int i = 0; i < 4; i++)
        #pragma unroll
        for (int j = 0; j < 4; j++)
            #pragma unroll
            for (int t = 0; t < 4; t++) acc[i][j][t] = 0.f;

    for (int k0 = 0; k0 < K; k0 += 16) {
        float4 a0 = *(const float4*)(Ag + k0);
        float4 a1 = *(const float4*)(Ag + k0 + 4);
        float4 b0 = *(const float4*)(Bg + k0);
        float4 b1 = *(const float4*)(Bg + k0 + 4);
        __syncthreads();
        As[kq+0][lrow] = f2tf32f(a0.x); As[kq+1][lrow] = f2tf32f(a0.y);
        As[kq+2][lrow] = f2tf32f(a0.z); As[kq+3][lrow] = f2tf32f(a0.w);
        As[kq+4][lrow] = f2tf32f(a1.x); As[kq+5][lrow] = f2tf32f(a1.y);
        As[kq+6][lrow] = f2tf32f(a1.z); As[kq+7][lrow] = f2tf32f(a1.w);
        Bs[kq+0][lrow] = f2tf32f(b0.x); Bs[kq+1][lrow] = f2tf32f(b0.y);
        Bs[kq+2][lrow] = f2tf32f(b0.z); Bs[kq+3][lrow] = f2tf32f(b0.w);
        Bs[kq+4][lrow] = f2tf32f(b1.x); Bs[kq+5][lrow] = f2tf32f(b1.y);
        Bs[kq+6][lrow] = f2tf32f(b1.z); Bs[kq+7][lrow] = f2tf32f(b1.w);
        __syncthreads();

        #pragma unroll
        for (int ks = 0; ks < 2; ks++) {
            const int kb = ks * 8;
            unsigned af[4][4], bf[4][2];
            #pragma unroll
            for (int mf = 0; mf < 4; mf++) {
                int r0 = wm + mf*16 + g;
                af[mf][0] = __float_as_uint(As[kb+tg  ][r0  ]);
                af[mf][1] = __float_as_uint(As[kb+tg  ][r0+8]);
                af[mf][2] = __float_as_uint(As[kb+tg+4][r0  ]);
                af[mf][3] = __float_as_uint(As[kb+tg+4][r0+8]);
            }
            #pragma unroll
            for (int nf = 0; nf < 4; nf++) {
                int cn = wn + nf*8 + g;
                bf[nf][0] = __float_as_uint(Bs[kb+tg  ][cn]);
                bf[nf][1] = __float_as_uint(Bs[kb+tg+4][cn]);
            }
            #pragma unroll
            for (int mf = 0; mf < 4; mf++)
                #pragma unroll
                for (int nf = 0; nf < 4; nf++)
                    mma_tf32(acc[mf][nf], af[mf], bf[nf][0], bf[nf][1]);
        }
    }

    #pragma unroll
    for (int mf = 0; mf < 4; mf++) {
        int r = brow + wm + mf*16 + g;
        #pragma unroll
        for (int nf = 0; nf < 4; nf++) {
            int cn = bcol + wn + nf*8 + tg*2;
            *(float2*)(C + (size_t)r * N + cn)     = make_float2(acc[mf][nf][0], acc[mf][nf][1]);
            *(float2*)(C + (size_t)(r+8) * N + cn) = make_float2(acc[mf][nf][2], acc[mf][nf][3]);
        }
    }
}

// ---------------- RMS helpers ----------------
__device__ __forceinline__ void rms_row_dev(float* p, const float* g, int C, int tid, float* red)
{
    float ss = 0.f;
    for (int i = tid; i < C; i += 128) { float v = p[i]; ss = fmaf(v, v, ss); }
    #pragma unroll
    for (int o = 16; o; o >>= 1) ss += __shfl_xor_sync(0xffffffffu, ss, o);
    if ((tid & 31) == 0) red[tid >> 5] = ss;
    __syncthreads();
    ss = red[0] + red[1] + red[2] + red[3];
    float r = rsqrtf(ss / C + 1e-6f);
    for (int i = tid; i < C; i += 128) p[i] = p[i] * r * g[i];
    __syncthreads();
}

// one launch: rms on q row (512), k row (128), v row (128)
__global__ __launch_bounds__(128) void rms3_kernel(
    float* __restrict__ q, float* __restrict__ k, float* __restrict__ v,
    const float* __restrict__ gl, const float* __restrict__ gkv)
{
    __shared__ float red[4];
    size_t row = blockIdx.x;
    int tid = threadIdx.x;
    rms_row_dev(q + row * 512, gl,  512, tid, red);
    rms_row_dev(k + row * 128, gkv, 128, tid, red);
    rms_row_dev(v + row * 128, gkv, 128, tid, red);
}

__global__ __launch_bounds__(128) void rms_kernel(
    float* __restrict__ buf, const float* __restrict__ g, int C)
{
    __shared__ float red[4];
    size_t row = blockIdx.x;
    float* p = buf + row * C;
    int tid = threadIdx.x;
    float ss = 0.f;
    for (int i = tid; i < C; i += 128) { float v = p[i]; ss = fmaf(v, v, ss); }
    #pragma unroll
    for (int o = 16; o; o >>= 1) ss += __shfl_xor_sync(0xffffffffu, ss, o);
    if ((tid & 31) == 0) red[tid >> 5] = ss;
    __syncthreads();
    ss = red[0] + red[1] + red[2] + red[3];
    float r = rsqrtf(ss / C + 1e-6f);
    for (int i = tid; i < C; i += 128) p[i] = p[i] * r * g[i];
}

// ---------------- fused middle: conv + rms + cross-mix + post-rms + head-norm + rope ----------------
__global__ __launch_bounds__(128) void mid_kernel(
    const float* __restrict__ qpre, const float* __restrict__ kpre, const float* __restrict__ vbuf,
    const float* __restrict__ cqw,  const float* __restrict__ ckw,
    const float* __restrict__ gconv, const float* __restrict__ gkconv,
    const float* __restrict__ gpostq, const float* __restrict__ gpostk,
    const float* __restrict__ ktemp,
    float* __restrict__ qf, float* __restrict__ kf, float* __restrict__ vf)
{
    int bs  = blockIdx.x;
    int b   = bs >> 11, s = bs & 2047;
    int tid = threadIdx.x;

    __shared__ float sq[3][512];
    __shared__ float sk[3][128];
    __shared__ float qc[512], kc[128];
    __shared__ float qm[32], km[32];
    __shared__ float red[4];
    __shared__ float sclq[16], sclk[4];
    __shared__ float s_rq, s_rk, s_r2q, s_r2k;

    for (int t = 0; t < 3; t++) {
        int srow = s - 2 + t;
        if (srow >= 0) {
            const float* srcq = qpre + ((size_t)b * 2048 + srow) * 512;
            for (int i = tid; i < 512; i += 128) sq[t][i] = srcq[i];
            const float* srck = kpre + ((size_t)b * 2048 + srow) * 128;
            sk[t][tid] = srck[tid];
        } else {
            for (int i = tid; i < 512; i += 128) sq[t][i] = 0.f;
            sk[t][tid] = 0.f;
        }
    }
    __syncthreads();

    for (int c = tid; c < 512; c += 128) {
        int gb = (c >> 5) << 5;
        const float* w = cqw + c * 96;
        float a = 0.f;
        #pragma unroll
        for (int i = 0; i < 32; i++) {
            int ch = gb + i;
            a = fmaf(w[i*3+0], sq[0][ch], a);
            a = fmaf(w[i*3+1], sq[1][ch], a);
            a = fmaf(w[i*3+2], sq[2][ch], a);
        }
        qc[c] = a;
    }
    {
        int c = tid; int gb = (c >> 5) << 5;
        const float* w = ckw + c * 96;
        float a = 0.f;
        #pragma unroll
        for (int i = 0; i < 32; i++) {
            int ch = gb + i;
            a = fmaf(w[i*3+0], sk[0][ch], a);
            a = fmaf(w[i*3+1], sk[1][ch], a);
            a = fmaf(w[i*3+2], sk[2][ch], a);
        }
        kc[c] = a;
    }
    if (tid < 32) {
        float a = 0.f;
        #pragma unroll
        for (int h = 0; h < 16; h++) a += sq[2][h*32 + tid];
        qm[tid] = a * (1.0f/16.0f);
        float bb = 0.f;
        #pragma unroll
        for (int g2 = 0; g2 < 4; g2++) bb += sk[2][g2*32 + tid];
        km[tid] = bb * 0.25f;
    }
    __syncthreads();

    float pq = 0.f;
    for (int i = tid; i < 512; i += 128) pq = fmaf(qc[i], qc[i], pq);
    float pk = kc[tid] * kc[tid];
    #pragma unroll
    for (int o = 16; o; o >>= 1) pq += __shfl_xor_sync(0xffffffffu, pq, o);
    if ((tid & 31) == 0) red[tid >> 5] = pq;
    __syncthreads();
    if (tid == 0) s_rq = rsqrtf((red[0]+red[1]+red[2]+red[3]) * (1.f/512.f) + 1e-6f);
    __syncthreads();
    #pragma unroll
    for (int o = 16; o; o >>= 1) pk += __shfl_xor_sync(0xffffffffu, pk, o);
    if ((tid & 31) == 0) red[tid >> 5] = pk;
    __syncthreads();
    if (tid == 0) s_rk = rsqrtf((red[0]+red[1]+red[2]+red[3]) * (1.f/128.f) + 1e-6f);
    __syncthreads();
    float rq = s_rq, rk = s_rk;

    for (int i = tid; i < 512; i += 128) qc[i] = qc[i] * rq * gconv[i]  + 0.25f * km[i & 31];
    kc[tid] = kc[tid] * rk * gkconv[tid] + 0.25f * qm[tid & 31];
    __syncthreads();

    float p2q = 0.f;
    for (int i = tid; i < 512; i += 128) p2q = fmaf(qc[i], qc[i], p2q);
    float p2k = kc[tid] * kc[tid];
    #pragma unroll
    for (int o = 16; o; o >>= 1) p2q += __shfl_xor_sync(0xffffffffu, p2q, o);
    if ((tid & 31) == 0) red[tid >> 5] = p2q;
    __syncthreads();
    if (tid == 0) s_r2q = rsqrtf((red[0]+red[1]+red[2]+red[3]) * (1.f/512.f) + 1e-6f);
    __syncthreads();
    #pragma unroll
    for (int o = 16; o; o >>= 1) p2k += __shfl_xor_sync(0xffffffffu, p2k, o);
    if ((tid & 31) == 0) red[tid >> 5] = p2k;
    __syncthreads();
    if (tid == 0) s_r2k = rsqrtf((red[0]+red[1]+red[2]+red[3]) * (1.f/128.f) + 1e-6f);
    __syncthreads();
    float r2q = s_r2q, r2k = s_r2k;
    for (int i = tid; i < 512; i += 128) qc[i] = qc[i] * r2q * gpostq[i];
    kc[tid] = kc[tid] * r2k * gpostk[tid];
    __syncthreads();

    if (tid < 16) {
        float a = 0.f;
        #pragma unroll
        for (int d = 0; d < 32; d++) { float v = qc[tid*32 + d]; a = fmaf(v, v, a); }
        sclq[tid] = 5.656854249492381f / fmaxf(sqrtf(a), 1e-12f);
    }
    if (tid >= 16 && tid < 20) {
        int g2 = tid - 16; float a = 0.f;
        #pragma unroll
        for (int d = 0; d < 32; d++) { float v = kc[g2*32 + d]; a = fmaf(v, v, a); }
        sclk[g2] = 5.656854249492381f * ktemp[0] / fmaxf(sqrtf(a), 1e-12f);
    }
    __syncthreads();

    for (int p = tid; p < 256; p += 128) {
        int h = p >> 4, d2 = p & 15;
        float fr = powf(10000.f, -(float)d2 * (1.f/16.f));
        float ang = (float)s * fr;
        float sn, cs; sincosf(ang, &sn, &cs);
        float scl = sclq[h];
        float x0 = qc[h*32 + 2*d2]     * scl;
        float x1 = qc[h*32 + 2*d2 + 1] * scl;
        float* dst = qf + (((size_t)(b*16 + h)) * 2048 + s) * 32 + 2*d2;
        dst[0] = x0*cs - x1*sn;
        dst[1] = x0*sn + x1*cs;
    }
    if (tid < 64) {
        int g2 = tid >> 4, d2 = tid & 15;
        float fr = powf(10000.f, -(float)d2 * (1.f/16.f));
        float ang = (float)s * fr;
        float sn, cs; sincosf(ang, &sn, &cs);
        float scl = sclk[g2];
        float x0 = kc[g2*32 + 2*d2]     * scl;
        float x1 = kc[g2*32 + 2*d2 + 1] * scl;
        float* dst = kf + (((size_t)(b*4 + g2)) * 2048 + s) * 32 + 2*d2;
        dst[0] = x0*cs - x1*sn;
        dst[1] = x0*sn + x1*cs;
    }
    {
        const float* vr = vbuf + ((size_t)b * 2048 + s) * 128;
        float vv = vr[tid];
        int g2 = tid >> 5, d = tid & 31;
        vf[(((size_t)(b*4 + g2)) * 2048 + s) * 32 + d] = vv;
    }
}

// ---------------- tensor-core flash attention (causal, GQA) ----------------
// block: 64 q-rows, 128 threads = 4 warps, warp w owns rows [16w,16w+16).
// QK: mma.m16n8k8 tf32; PV: mma.m16n8k16 fp16 (P frags == QK C frags, no shuffle).
__global__ __launch_bounds__(128, 4) void attn_mma_kernel(
    const float* __restrict__ qf, const float* __restrict__ kf, const float* __restrict__ vf,
    float* __restrict__ attn)
{
    const int bh = blockIdx.x;            // b*16 + h
    const int qt = blockIdx.y;
    const int b = bh >> 4, h = bh & 15;
    const int kvh = h >> 2;
    const int tid = threadIdx.x;
    const int w = tid >> 5, lane = tid & 31;
    const int g = lane >> 2, tg = lane & 3;

    __shared__ float  Ks[64][40];         // [key][d] tf32, stride 40 words: banks 8g+tg bijective
    __shared__ __half Vts[32][72];        // [d][key] fp16, stride 72 halves: banks 4g+tg bijective

    const float scale = 0.17677669529663687f;  // 1/sqrt(32)
    const int r0 = qt*64 + w*16 + g;           // global q row for c0/c1 lanes (r0+8 for c2/c3)

    // Q a-frags: 4 d-chunks of k8
    unsigned qa[4][4];
    {
        const float* qb = qf + ((size_t)bh * 2048) * 32;
        #pragma unroll
        for (int ch = 0; ch < 4; ch++) {
            qa[ch][0] = f2tf32u(qb[(size_t)r0*32     + ch*8 + tg    ] * scale);
            qa[ch][1] = f2tf32u(qb[(size_t)(r0+8)*32 + ch*8 + tg    ] * scale);
            qa[ch][2] = f2tf32u(qb[(size_t)r0*32     + ch*8 + tg + 4] * scale);
            qa[ch][3] = f2tf32u(qb[(size_t)(r0+8)*32 + ch*8 + tg + 4] * scale);
        }
    }

    float m0 = -3.0e38f, m1 = -3.0e38f, l0 = 0.f, l1 = 0.f;
    float ot[4][4];
    #pragma unroll
    for (int nt = 0; nt < 4; nt++)
        #pragma unroll
        for (int t = 0; t < 4; t++) ot[nt][t] = 0.f;

    const float* kbase = kf + (size_t)(b*4 + kvh) * 2048 * 32;
    const float* vbase = vf + (size_t)(b*4 + kvh) * 2048 * 32;

    for (int j = 0; j <= qt; j++) {
        // --- load K tile (cvt to tf32) ---
        #pragma unroll
        for (int i = 0; i < 4; i++) {
            int idx = tid + i*128;            // 0..511
            int row = idx >> 3, dq = (idx & 7) * 4;
            float4 kv = *(const float4*)(kbase + (size_t)(j*64 + row)*32 + dq);
            float4 kt;
            kt.x = f2tf32f(kv.x); kt.y = f2tf32f(kv.y);
            kt.z = f2tf32f(kv.z); kt.w = f2tf32f(kv.w);
            *(float4*)&Ks[row][dq] = kt;
        }
        // --- load V tile transposed to fp16: Vts[d][key] ---
        #pragma unroll
        for (int i = 0; i < 2; i++) {
            int idx = tid + i*128;            // 0..255
            int c = idx >> 5, pr = idx & 31;  // d-chunk c (4 d's), key pair (2pr,2pr+1)
            const float* vp = vbase + (size_t)(j*64 + 2*pr)*32 + 4*c;
            float4 v0 = *(const float4*)vp;
            float4 v1 = *(const float4*)(vp + 32);
            *(__half2*)&Vts[4*c+0][2*pr] = __floats2half2_rn(v0.x, v1.x);
            *(__half2*)&Vts[4*c+1][2*pr] = __floats2half2_rn(v0.y, v1.y);
            *(__half2*)&Vts[4*c+2][2*pr] = __floats2half2_rn(v0.z, v1.z);
            *(__half2*)&Vts[4*c+3][2*pr] = __floats2half2_rn(v0.w, v1.w);
        }
        __syncthreads();

        // --- S = Q K^T  (16 rows x 64 cols per warp) ---
        float sc[8][4];
        #pragma unroll
        for (int nf = 0; nf < 8; nf++)
            #pragma unroll
            for (int t = 0; t < 4; t++) sc[nf][t] = 0.f;
        #pragma unroll
        for (int ch = 0; ch < 4; ch++) {
            #pragma unroll
            for (int nf = 0; nf < 8; nf++) {
                unsigned b0 = __float_as_uint(Ks[nf*8 + g][ch*8 + tg    ]);
                unsigned b1 = __float_as_uint(Ks[nf*8 + g][ch*8 + tg + 4]);
                mma_tf32(sc[nf], qa[ch], b0, b1);
            }
        }

        // --- causal mask (diagonal tile only) ---
        if (j == qt) {
            int cb = qt*64;
            #pragma unroll
            for (int nf = 0; nf < 8; nf++) {
                #pragma unroll
                for (int bb = 0; bb < 2; bb++) {
                    int col = cb + nf*8 + 2*tg + bb;
                    if (col > r0)     sc[nf][bb]     = -1.0e30f;
                    if (col > r0 + 8) sc[nf][2 + bb] = -1.0e30f;
                }
            }
        }

        // --- online softmax (rows g and g+8) ---
        float ml0 = -1.0e30f, ml1 = -1.0e30f;
        #pragma unroll
        for (int nf = 0; nf < 8; nf++) {
            ml0 = fmaxf(ml0, fmaxf(sc[nf][0], sc[nf][1]));
            ml1 = fmaxf(ml1, fmaxf(sc[nf][2], sc[nf][3]));
        }
        ml0 = fmaxf(ml0, __shfl_xor_sync(0xffffffffu, ml0, 1));
        ml0 = fmaxf(ml0, __shfl_xor_sync(0xffffffffu, ml0, 2));
        ml1 = fmaxf(ml1, __shfl_xor_sync(0xffffffffu, ml1, 1));
        ml1 = fmaxf(ml1, __shfl_xor_sync(0xffffffffu, ml1, 2));
        float mn0 = fmaxf(m0, ml0), mn1 = fmaxf(m1, ml1);
        float al0 = __expf(m0 - mn0), al1 = __expf(m1 - mn1);
        float ll0 = 0.f, ll1 = 0.f;
        #pragma unroll
        for (int nf = 0; nf < 8; nf++) {
            sc[nf][0] = __expf(sc[nf][0] - mn0); ll0 += sc[nf][0];
            sc[nf][1] = __expf(sc[nf][1] - mn0); ll0 += sc[nf][1];
            sc[nf][2] = __expf(sc[nf][2] - mn1); ll1 += sc[nf][2];
            sc[nf][3] = __expf(sc[nf][3] - mn1); ll1 += sc[nf][3];
        }
        ll0 += __shfl_xor_sync(0xffffffffu, ll0, 1);
        ll0 += __shfl_xor_sync(0xffffffffu, ll0, 2);
        ll1 += __shfl_xor_sync(0xffffffffu, ll1, 1);
        ll1 += __shfl_xor_sync(0xffffffffu, ll1, 2);
        l0 = l0 * al0 + ll0; m0 = mn0;
        l1 = l1 * al1 + ll1; m1 = mn1;

        // --- rescale accumulators ---
        #pragma unroll
        for (int nt = 0; nt < 4; nt++) {
            ot[nt][0] *= al0; ot[nt][1] *= al0;
            ot[nt][2] *= al1; ot[nt][3] *= al1;
        }

        // --- P frags (fp16; layout matches QK C frags) + PV mma ---
        #pragma unroll
        for (int kc = 0; kc < 4; kc++) {
            unsigned pa[4];
            __half2 h0 = __floats2half2_rn(sc[2*kc][0],   sc[2*kc][1]);
            __half2 h1 = __floats2half2_rn(sc[2*kc][2],   sc[2*kc][3]);
            __half2 h2 = __floats2half2_rn(sc[2*kc+1][0], sc[2*kc+1][1]);
            __half2 h3 = __floats2half2_rn(sc[2*kc+1][2], sc[2*kc+1][3]);
            pa[0] = *(unsigned*)&h0; pa[1] = *(unsigned*)&h1;
            pa[2] = *(unsigned*)&h2; pa[3] = *(unsigned*)&h3;
            #pragma unroll
            for (int nt = 0; nt < 4; nt++) {
                unsigned b0 = *(const unsigned*)&Vts[nt*8 + g][kc*16 + 2*tg    ];
                unsigned b1 = *(const unsigned*)&Vts[nt*8 + g][kc*16 + 8 + 2*tg];
                mma_f16(ot[nt], pa, b0, b1);
            }
        }
        __syncthreads();
    }

    // --- epilogue: normalize and store to [B,S,512] ---
    float inv0 = 1.f / l0, inv1 = 1.f / l1;
    float* ob = attn + ((size_t)b * 2048) * 512 + h*32;
    #pragma unroll
    for (int nt = 0; nt < 4; nt++) {
        *(float2*)(ob + (size_t)r0*512     + nt*8 + 2*tg) = make_float2(ot[nt][0]*inv0, ot[nt][1]*inv0);
        *(float2*)(ob + (size_t)(r0+8)*512 + nt*8 + 2*tg) = make_float2(ot[nt][2]*inv1, ot[nt][3]*inv1);
    }
}

// ---------------- launcher ----------------
extern "C" void kernel_launch(void* const* d_in, const int* in_sizes, int n_in,
                              void* d_out, int out_size)
{
    const float* x       = (const float*)d_in[0];
    const float* w_q     = (const float*)d_in[1];
    const float* w_k     = (const float*)d_in[2];
    const float* w_v     = (const float*)d_in[3];
    const float* g_lat   = (const float*)d_in[4];
    const float* g_kv    = (const float*)d_in[5];
    const float* cqw     = (const float*)d_in[6];
    const float* ckw     = (const float*)d_in[7];
    const float* gconv   = (const float*)d_in[8];
    const float* gkconv  = (const float*)d_in[9];
    const float* gpostq  = (const float*)d_in[10];
    const float* gpostk  = (const float*)d_in[11];
    const float* ktemp   = (const float*)d_in[12];
    const float* gpreout = (const float*)d_in[13];
    const float* w_o     = (const float*)d_in[14];
    float* out = (float*)d_out;

    float *qpre, *kpre, *vbuf, *qf, *kf, *vf, *attn;
    cudaGetSymbolAddress((void**)&qpre, g_qpre);
    cudaGetSymbolAddress((void**)&kpre, g_kpre);
    cudaGetSymbolAddress((void**)&vbuf, g_vbuf);
    cudaGetSymbolAddress((void**)&qf,   g_qf);
    cudaGetSymbolAddress((void**)&kf,   g_kf);
    cudaGetSymbolAddress((void**)&vf,   g_vf);
    cudaGetSymbolAddress((void**)&attn, g_attn);

    const int M = NB * SEQ;  // 8192

    // launches 0-2: QKV projections (tf32 tensor cores)
    gemm_tf32<<<dim3(LATD/128, M/128), 256>>>(x, w_q, qpre, M, LATD, DIMM);
    gemm_tf32<<<dim3(KVDD/128, M/128), 256>>>(x, w_k, kpre, M, KVDD, DIMM);
    gemm_tf32<<<dim3(KVDD/128, M/128), 256>>>(x, w_v, vbuf, M, KVDD, DIMM);

    // launch 3: fused first RMS norms (q, k, v)
    rms3_kernel<<<M, 128>>>(qpre, kpre, vbuf, g_lat, g_kv);

    // launch 4: fused conv / mix / post-rms / head-norm / rope / relayout
    mid_kernel<<<M, 128>>>(qpre, kpre, vbuf, cqw, ckw, gconv, gkconv,
                           gpostq, gpostk, ktemp, qf, kf, vf);

    // launch 5 (ncu -s 5 captures this): causal GQA attention, tensor cores
    attn_mma_kernel<<<dim3(NB*NHH, SEQ/64), 128>>>(qf, kf, vf, attn);

    // launch 6: pre-output RMS
    rms_kernel<<<M, 128>>>(attn, gpreout, LATD);

    // launch 7: output projection
    gemm_tf32<<<dim3(DIMM/128, M/128), 256>>>(attn, w_o, out, M, DIMM, LATD);
}

// round 8
// speedup vs baseline: 4.5581x; 2.4834x over previous
#include <cuda_runtime.h>
#include <cuda_fp16.h>
#include <math.h>

#define NB   4
#define SEQ  2048
#define DIMM 2048
#define LATD 512
#define KVDD 128
#define NHH  16
#define NKVV 4
#define HDD  32
#define TOK  8

// ---------------- scratch (device globals; no allocations allowed) ----------------
__device__ float g_qpre[NB*SEQ*LATD];     // q after proj+rms  [B,S,512]
__device__ float g_kpre[NB*SEQ*KVDD];     // k after proj+rms  [B,S,128]
__device__ float g_vbuf[NB*SEQ*KVDD];     // v after proj+rms  [B,S,128]
__device__ float g_qf  [NB*NHH*SEQ*HDD];  // final q [B,16,S,32]
__device__ float g_kf  [NB*NKVV*SEQ*HDD]; // final k [B,4,S,32]
__device__ float g_vf  [NB*NKVV*SEQ*HDD]; // final v [B,4,S,32]
__device__ float g_attn[NB*SEQ*LATD];     // attention out [B,S,512]

__device__ __forceinline__ float f2tf32f(float f) {
    unsigned u; asm("cvt.rna.tf32.f32 %0, %1;" : "=r"(u) : "f"(f));
    return __uint_as_float(u);
}
__device__ __forceinline__ unsigned f2tf32u(float f) {
    unsigned u; asm("cvt.rna.tf32.f32 %0, %1;" : "=r"(u) : "f"(f));
    return u;
}

// ---------------- mma helpers ----------------
__device__ __forceinline__ void mma_tf32(float* c, const unsigned* a, unsigned b0, unsigned b1) {
    asm volatile(
        "mma.sync.aligned.m16n8k8.row.col.f32.tf32.tf32.f32 "
        "{%0,%1,%2,%3},{%4,%5,%6,%7},{%8,%9},{%0,%1,%2,%3};"
        : "+f"(c[0]), "+f"(c[1]), "+f"(c[2]), "+f"(c[3])
        : "r"(a[0]), "r"(a[1]), "r"(a[2]), "r"(a[3]), "r"(b0), "r"(b1));
}
__device__ __forceinline__ void mma_f16(float* c, const unsigned* a, unsigned b0, unsigned b1) {
    asm volatile(
        "mma.sync.aligned.m16n8k16.row.col.f32.f16.f16.f32 "
        "{%0,%1,%2,%3},{%4,%5,%6,%7},{%8,%9},{%0,%1,%2,%3};"
        : "+f"(c[0]), "+f"(c[1]), "+f"(c[2]), "+f"(c[3])
        : "r"(a[0]), "r"(a[1]), "r"(a[2]), "r"(a[3]), "r"(b0), "r"(b1));
}

__device__ __forceinline__ void cp16(unsigned smem_addr, const float* gptr) {
    asm volatile("cp.async.ca.shared.global [%0], [%1], 16;" :: "r"(smem_addr), "l"(gptr));
}

// ---------------- pipelined tf32 tensor-core GEMM: C[M,N] = A[M,K] @ B[N,K]^T ----------------
// BM=BN=128, BK=16, 256 threads, cp.async 2-stage double buffer.
// smem [m][k] stride 20 words: 16B-aligned rows, conflict-free fragment loads.
__global__ __launch_bounds__(256) void gemm_tf32(
    const float* __restrict__ A, const float* __restrict__ B, float* __restrict__ C,
    int M, int N, int K)
{
    __shared__ float As[2][128*20];
    __shared__ float Bs[2][128*20];

    const int tid  = threadIdx.x;
    const int warp = tid >> 5, lane = tid & 31;
    const int g = lane >> 2, tg = lane & 3;
    const int wm = (warp >> 2) * 64;
    const int wn = (warp & 3) * 32;
    const int brow = blockIdx.y * 128;
    const int bcol = blockIdx.x * 128;

    // load mapping: 512 16B-chunks per operand; thread does chunks tid, tid+256
    const int lr = tid >> 2;             // 0..63
    const int cq = (tid & 3) * 4;        // 0,4,8,12
    const float* Ag0 = A + (size_t)(brow + lr)      * K + cq;
    const float* Ag1 = A + (size_t)(brow + lr + 64) * K + cq;
    const float* Bg0 = B + (size_t)(bcol + lr)      * K + cq;
    const float* Bg1 = B + (size_t)(bcol + lr + 64) * K + cq;
    const int so0 = lr * 20 + cq;
    const int so1 = (lr + 64) * 20 + cq;

    unsigned sA0[2], sA1[2], sB0[2], sB1[2];
    #pragma unroll
    for (int st = 0; st < 2; st++) {
        sA0[st] = (unsigned)__cvta_generic_to_shared(&As[st][so0]);
        sA1[st] = (unsigned)__cvta_generic_to_shared(&As[st][so1]);
        sB0[st] = (unsigned)__cvta_generic_to_shared(&Bs[st][so0]);
        sB1[st] = (unsigned)__cvta_generic_to_shared(&Bs[st][so1]);
    }

    float acc[4][4][4];
    #pragma unroll
    for (int i = 0; i < 4; i++)
        #pragma unroll
        for (int j = 0; j < 4; j++)
            #pragma unroll
            for (int t = 0; t < 4; t++) acc[i][j][t] = 0.f;

    const int nk = K >> 4;

    // prologue: stage 0 <- tile 0
    cp16(sA0[0], Ag0); cp16(sA1[0], Ag1);
    cp16(sB0[0], Bg0); cp16(sB1[0], Bg1);
    asm volatile("cp.async.commit_group;");

    for (int t = 0; t < nk; t++) {
        const int cur = t & 1;
        if (t + 1 < nk) {
            const int nxt = (t + 1) & 1;
            const int k0 = (t + 1) << 4;
            cp16(sA0[nxt], Ag0 + k0); cp16(sA1[nxt], Ag1 + k0);
            cp16(sB0[nxt], Bg0 + k0); cp16(sB1[nxt], Bg1 + k0);
        }
        asm volatile("cp.async.commit_group;");
        asm volatile("cp.async.wait_group 1;");
        __syncthreads();

        const float* as = As[cur];
        const float* bs = Bs[cur];
        #pragma unroll
        for (int ks = 0; ks < 2; ks++) {
            const int kb = ks * 8;
            unsigned af[4][4], bf[4][2];
            #pragma unroll
            for (int mf = 0; mf < 4; mf++) {
                int r0 = wm + mf*16 + g;
                af[mf][0] = f2tf32u(as[r0*20     + kb + tg    ]);
                af[mf][1] = f2tf32u(as[(r0+8)*20 + kb + tg    ]);
                af[mf][2] = f2tf32u(as[r0*20     + kb + tg + 4]);
                af[mf][3] = f2tf32u(as[(r0+8)*20 + kb + tg + 4]);
            }
            #pragma unroll
            for (int nf = 0; nf < 4; nf++) {
                int cn = wn + nf*8 + g;
                bf[nf][0] = f2tf32u(bs[cn*20 + kb + tg    ]);
                bf[nf][1] = f2tf32u(bs[cn*20 + kb + tg + 4]);
            }
            #pragma unroll
            for (int mf = 0; mf < 4; mf++)
                #pragma unroll
                for (int nf = 0; nf < 4; nf++)
                    mma_tf32(acc[mf][nf], af[mf], bf[nf][0], bf[nf][1]);
        }
        __syncthreads();
    }

    #pragma unroll
    for (int mf = 0; mf < 4; mf++) {
        int r = brow + wm + mf*16 + g;
        #pragma unroll
        for (int nf = 0; nf < 4; nf++) {
            int cn = bcol + wn + nf*8 + tg*2;
            *(float2*)(C + (size_t)r * N + cn)     = make_float2(acc[mf][nf][0], acc[mf][nf][1]);
            *(float2*)(C + (size_t)(r+8) * N + cn) = make_float2(acc[mf][nf][2], acc[mf][nf][3]);
        }
    }
}

// ---------------- RMS helpers ----------------
__device__ __forceinline__ void rms_row_dev(float* p, const float* g, int C, int tid, float* red)
{
    float ss = 0.f;
    for (int i = tid; i < C; i += 128) { float v = p[i]; ss = fmaf(v, v, ss); }
    #pragma unroll
    for (int o = 16; o; o >>= 1) ss += __shfl_xor_sync(0xffffffffu, ss, o);
    if ((tid & 31) == 0) red[tid >> 5] = ss;
    __syncthreads();
    ss = red[0] + red[1] + red[2] + red[3];
    float r = rsqrtf(ss / C + 1e-6f);
    for (int i = tid; i < C; i += 128) p[i] = p[i] * r * g[i];
    __syncthreads();
}

__global__ __launch_bounds__(128) void rms3_kernel(
    float* __restrict__ q, float* __restrict__ k, float* __restrict__ v,
    const float* __restrict__ gl, const float* __restrict__ gkv)
{
    __shared__ float red[4];
    size_t row = blockIdx.x;
    int tid = threadIdx.x;
    rms_row_dev(q + row * 512, gl,  512, tid, red);
    rms_row_dev(k + row * 128, gkv, 128, tid, red);
    rms_row_dev(v + row * 128, gkv, 128, tid, red);
}

__global__ __launch_bounds__(128) void rms_kernel(
    float* __restrict__ buf, const float* __restrict__ g, int C)
{
    __shared__ float red[4];
    size_t row = blockIdx.x;
    float* p = buf + row * C;
    int tid = threadIdx.x;
    float ss = 0.f;
    for (int i = tid; i < C; i += 128) { float v = p[i]; ss = fmaf(v, v, ss); }
    #pragma unroll
    for (int o = 16; o; o >>= 1) ss += __shfl_xor_sync(0xffffffffu, ss, o);
    if ((tid & 31) == 0) red[tid >> 5] = ss;
    __syncthreads();
    ss = red[0] + red[1] + red[2] + red[3];
    float r = rsqrtf(ss / C + 1e-6f);
    for (int i = tid; i < C; i += 128) p[i] = p[i] * r * g[i];
}

// ---------------- fused middle, 8 tokens per block ----------------
// conv weights loaded once per 8 tokens (8x less L2 traffic), then the
// per-token reduction/rope pipeline runs sequentially.
__global__ __launch_bounds__(128) void mid_kernel(
    const float* __restrict__ qpre, const float* __restrict__ kpre, const float* __restrict__ vbuf,
    const float* __restrict__ cqw,  const float* __restrict__ ckw,
    const float* __restrict__ gconv, const float* __restrict__ gkconv,
    const float* __restrict__ gpostq, const float* __restrict__ gpostk,
    const float* __restrict__ ktemp,
    float* __restrict__ qf, float* __restrict__ kf, float* __restrict__ vf)
{
    int blk = blockIdx.x;                 // 1024 blocks
    int b   = blk >> 8;                   // 256 tiles per batch
    int s0  = (blk & 255) * TOK;
    int tid = threadIdx.x;

    __shared__ float sq[TOK+2][512];
    __shared__ float sk[TOK+2][128];
    __shared__ float qc[TOK][512];
    __shared__ float kcs[TOK][128];
    __shared__ float qm[TOK][32], km[TOK][32];
    __shared__ float red[4];
    __shared__ float sclq[16], sclk[4];
    __shared__ float s_rq, s_rk, s_r2q, s_r2k;

    // load TOK+2 causal rows
    for (int t = 0; t < TOK+2; t++) {
        int srow = s0 - 2 + t;
        if (srow >= 0) {
            const float* srcq = qpre + ((size_t)b * 2048 + srow) * 512;
            for (int i = tid; i < 512; i += 128) sq[t][i] = srcq[i];
            sk[t][tid] = kpre[((size_t)b * 2048 + srow) * 128 + tid];
        } else {
            for (int i = tid; i < 512; i += 128) sq[t][i] = 0.f;
            sk[t][tid] = 0.f;
        }
    }
    __syncthreads();

    // q conv: each thread 4 channels x 8 tokens; weights loaded once
    for (int c = tid; c < 512; c += 128) {
        int gb = (c >> 5) << 5;
        const float* w = cqw + c * 96;
        float a[TOK];
        #pragma unroll
        for (int t = 0; t < TOK; t++) a[t] = 0.f;
        for (int i = 0; i < 32; i++) {
            int ch = gb + i;
            float w0 = w[i*3], w1 = w[i*3+1], w2 = w[i*3+2];
            float r[TOK+2];
            #pragma unroll
            for (int t = 0; t < TOK+2; t++) r[t] = sq[t][ch];
            #pragma unroll
            for (int t = 0; t < TOK; t++)
                a[t] = fmaf(w0, r[t], fmaf(w1, r[t+1], fmaf(w2, r[t+2], a[t])));
        }
        #pragma unroll
        for (int t = 0; t < TOK; t++) qc[t][c] = a[t];
    }
    // k conv: one channel per thread
    {
        int c = tid, gb = (c >> 5) << 5;
        const float* w = ckw + c * 96;
        float a[TOK];
        #pragma unroll
        for (int t = 0; t < TOK; t++) a[t] = 0.f;
        for (int i = 0; i < 32; i++) {
            int ch = gb + i;
            float w0 = w[i*3], w1 = w[i*3+1], w2 = w[i*3+2];
            float r[TOK+2];
            #pragma unroll
            for (int t = 0; t < TOK+2; t++) r[t] = sk[t][ch];
            #pragma unroll
            for (int t = 0; t < TOK; t++)
                a[t] = fmaf(w0, r[t], fmaf(w1, r[t+1], fmaf(w2, r[t+2], a[t])));
        }
        #pragma unroll
        for (int t = 0; t < TOK; t++) kcs[t][c] = a[t];
    }
    // head means of the pre-conv tensors (current rows)
    for (int p = tid; p < TOK*32; p += 128) {
        int t = p >> 5, d = p & 31;
        float a = 0.f;
        #pragma unroll
        for (int h = 0; h < 16; h++) a += sq[t+2][h*32 + d];
        qm[t][d] = a * (1.0f/16.0f);
        float bb = 0.f;
        #pragma unroll
        for (int g2 = 0; g2 < 4; g2++) bb += sk[t+2][g2*32 + d];
        km[t][d] = bb * 0.25f;
    }
    __syncthreads();

    const float kt0 = ktemp[0];

    for (int t = 0; t < TOK; t++) {
        int s = s0 + t;
        float* qcv = qc[t];
        float* kcv = kcs[t];

        // rms over conv outputs
        float pq = 0.f;
        for (int i = tid; i < 512; i += 128) pq = fmaf(qcv[i], qcv[i], pq);
        float pk = kcv[tid] * kcv[tid];
        #pragma unroll
        for (int o = 16; o; o >>= 1) pq += __shfl_xor_sync(0xffffffffu, pq, o);
        if ((tid & 31) == 0) red[tid >> 5] = pq;
        __syncthreads();
        if (tid == 0) s_rq = rsqrtf((red[0]+red[1]+red[2]+red[3]) * (1.f/512.f) + 1e-6f);
        __syncthreads();
        #pragma unroll
        for (int o = 16; o; o >>= 1) pk += __shfl_xor_sync(0xffffffffu, pk, o);
        if ((tid & 31) == 0) red[tid >> 5] = pk;
        __syncthreads();
        if (tid == 0) s_rk = rsqrtf((red[0]+red[1]+red[2]+red[3]) * (1.f/128.f) + 1e-6f);
        __syncthreads();
        float rq = s_rq, rk = s_rk;

        // rms gains + cross-mix (GAIN=0.25)
        for (int i = tid; i < 512; i += 128) qcv[i] = qcv[i] * rq * gconv[i]  + 0.25f * km[t][i & 31];
        kcv[tid] = kcv[tid] * rk * gkconv[tid] + 0.25f * qm[t][tid & 31];
        __syncthreads();

        // post-rms
        float p2q = 0.f;
        for (int i = tid; i < 512; i += 128) p2q = fmaf(qcv[i], qcv[i], p2q);
        float p2k = kcv[tid] * kcv[tid];
        #pragma unroll
        for (int o = 16; o; o >>= 1) p2q += __shfl_xor_sync(0xffffffffu, p2q, o);
        if ((tid & 31) == 0) red[tid >> 5] = p2q;
        __syncthreads();
        if (tid == 0) s_r2q = rsqrtf((red[0]+red[1]+red[2]+red[3]) * (1.f/512.f) + 1e-6f);
        __syncthreads();
        #pragma unroll
        for (int o = 16; o; o >>= 1) p2k += __shfl_xor_sync(0xffffffffu, p2k, o);
        if ((tid & 31) == 0) red[tid >> 5] = p2k;
        __syncthreads();
        if (tid == 0) s_r2k = rsqrtf((red[0]+red[1]+red[2]+red[3]) * (1.f/128.f) + 1e-6f);
        __syncthreads();
        float r2q = s_r2q, r2k = s_r2k;
        for (int i = tid; i < 512; i += 128) qcv[i] = qcv[i] * r2q * gpostq[i];
        kcv[tid] = kcv[tid] * r2k * gpostk[tid];
        __syncthreads();

        // per-head L2 norm -> scale to sqrt(HD) (k also * key_temp)
        if (tid < 16) {
            float a = 0.f;
            #pragma unroll
            for (int d = 0; d < 32; d++) { float v = qcv[tid*32 + d]; a = fmaf(v, v, a); }
            sclq[tid] = 5.656854249492381f / fmaxf(sqrtf(a), 1e-12f);
        }
        if (tid >= 16 && tid < 20) {
            int g2 = tid - 16; float a = 0.f;
            #pragma unroll
            for (int d = 0; d < 32; d++) { float v = kcv[g2*32 + d]; a = fmaf(v, v, a); }
            sclk[g2] = 5.656854249492381f * kt0 / fmaxf(sqrtf(a), 1e-12f);
        }
        __syncthreads();

        // rope + relayout
        for (int p = tid; p < 256; p += 128) {
            int h = p >> 4, d2 = p & 15;
            float fr = powf(10000.f, -(float)d2 * (1.f/16.f));
            float ang = (float)s * fr;
            float sn, cs; sincosf(ang, &sn, &cs);
            float scl = sclq[h];
            float x0 = qcv[h*32 + 2*d2]     * scl;
            float x1 = qcv[h*32 + 2*d2 + 1] * scl;
            float* dst = qf + (((size_t)(b*16 + h)) * 2048 + s) * 32 + 2*d2;
            dst[0] = x0*cs - x1*sn;
            dst[1] = x0*sn + x1*cs;
        }
        if (tid < 64) {
            int g2 = tid >> 4, d2 = tid & 15;
            float fr = powf(10000.f, -(float)d2 * (1.f/16.f));
            float ang = (float)s * fr;
            float sn, cs; sincosf(ang, &sn, &cs);
            float scl = sclk[g2];
            float x0 = kcv[g2*32 + 2*d2]     * scl;
            float x1 = kcv[g2*32 + 2*d2 + 1] * scl;
            float* dst = kf + (((size_t)(b*4 + g2)) * 2048 + s) * 32 + 2*d2;
            dst[0] = x0*cs - x1*sn;
            dst[1] = x0*sn + x1*cs;
        }
        {
            const float* vr = vbuf + ((size_t)b * 2048 + s) * 128;
            float vv = vr[tid];
            int g2 = tid >> 5, d = tid & 31;
            vf[(((size_t)(b*4 + g2)) * 2048 + s) * 32 + d] = vv;
        }
        __syncthreads();
    }
}

// ---------------- tensor-core flash attention (causal, GQA) ----------------
__global__ __launch_bounds__(128, 4) void attn_mma_kernel(
    const float* __restrict__ qf, const float* __restrict__ kf, const float* __restrict__ vf,
    float* __restrict__ attn)
{
    const int bh = blockIdx.x;            // b*16 + h
    const int qt = blockIdx.y;
    const int b = bh >> 4, h = bh & 15;
    const int kvh = h >> 2;
    const int tid = threadIdx.x;
    const int w = tid >> 5, lane = tid & 31;
    const int g = lane >> 2, tg = lane & 3;

    __shared__ float  Ks[64][40];
    __shared__ __half Vts[32][72];

    const float scale = 0.17677669529663687f;
    const int r0 = qt*64 + w*16 + g;

    unsigned qa[4][4];
    {
        const float* qb = qf + ((size_t)bh * 2048) * 32;
        #pragma unroll
        for (int ch = 0; ch < 4; ch++) {
            qa[ch][0] = f2tf32u(qb[(size_t)r0*32     + ch*8 + tg    ] * scale);
            qa[ch][1] = f2tf32u(qb[(size_t)(r0+8)*32 + ch*8 + tg    ] * scale);
            qa[ch][2] = f2tf32u(qb[(size_t)r0*32     + ch*8 + tg + 4] * scale);
            qa[ch][3] = f2tf32u(qb[(size_t)(r0+8)*32 + ch*8 + tg + 4] * scale);
        }
    }

    float m0 = -3.0e38f, m1 = -3.0e38f, l0 = 0.f, l1 = 0.f;
    float ot[4][4];
    #pragma unroll
    for (int nt = 0; nt < 4; nt++)
        #pragma unroll
        for (int t = 0; t < 4; t++) ot[nt][t] = 0.f;

    const float* kbase = kf + (size_t)(b*4 + kvh) * 2048 * 32;
    const float* vbase = vf + (size_t)(b*4 + kvh) * 2048 * 32;

    for (int j = 0; j <= qt; j++) {
        #pragma unroll
        for (int i = 0; i < 4; i++) {
            int idx = tid + i*128;
            int row = idx >> 3, dq = (idx & 7) * 4;
            float4 kv = *(const float4*)(kbase + (size_t)(j*64 + row)*32 + dq);
            float4 kt;
            kt.x = f2tf32f(kv.x); kt.y = f2tf32f(kv.y);
            kt.z = f2tf32f(kv.z); kt.w = f2tf32f(kv.w);
            *(float4*)&Ks[row][dq] = kt;
        }
        #pragma unroll
        for (int i = 0; i < 2; i++) {
            int idx = tid + i*128;
            int c = idx >> 5, pr = idx & 31;
            const float* vp = vbase + (size_t)(j*64 + 2*pr)*32 + 4*c;
            float4 v0 = *(const float4*)vp;
            float4 v1 = *(const float4*)(vp + 32);
            *(__half2*)&Vts[4*c+0][2*pr] = __floats2half2_rn(v0.x, v1.x);
            *(__half2*)&Vts[4*c+1][2*pr] = __floats2half2_rn(v0.y, v1.y);
            *(__half2*)&Vts[4*c+2][2*pr] = __floats2half2_rn(v0.z, v1.z);
            *(__half2*)&Vts[4*c+3][2*pr] = __floats2half2_rn(v0.w, v1.w);
        }
        __syncthreads();

        float sc[8][4];
        #pragma unroll
        for (int nf = 0; nf < 8; nf++)
            #pragma unroll
            for (int t = 0; t < 4; t++) sc[nf][t] = 0.f;
        #pragma unroll
        for (int ch = 0; ch < 4; ch++) {
            #pragma unroll
            for (int nf = 0; nf < 8; nf++) {
                unsigned b0 = __float_as_uint(Ks[nf*8 + g][ch*8 + tg    ]);
                unsigned b1 = __float_as_uint(Ks[nf*8 + g][ch*8 + tg + 4]);
                mma_tf32(sc[nf], qa[ch], b0, b1);
            }
        }

        if (j == qt) {
            int cb = qt*64;
            #pragma unroll
            for (int nf = 0; nf < 8; nf++) {
                #pragma unroll
                for (int bb = 0; bb < 2; bb++) {
                    int col = cb + nf*8 + 2*tg + bb;
                    if (col > r0)     sc[nf][bb]     = -1.0e30f;
                    if (col > r0 + 8) sc[nf][2 + bb] = -1.0e30f;
                }
            }
        }

        float ml0 = -1.0e30f, ml1 = -1.0e30f;
        #pragma unroll
        for (int nf = 0; nf < 8; nf++) {
            ml0 = fmaxf(ml0, fmaxf(sc[nf][0], sc[nf][1]));
            ml1 = fmaxf(ml1, fmaxf(sc[nf][2], sc[nf][3]));
        }
        ml0 = fmaxf(ml0, __shfl_xor_sync(0xffffffffu, ml0, 1));
        ml0 = fmaxf(ml0, __shfl_xor_sync(0xffffffffu, ml0, 2));
        ml1 = fmaxf(ml1, __shfl_xor_sync(0xffffffffu, ml1, 1));
        ml1 = fmaxf(ml1, __shfl_xor_sync(0xffffffffu, ml1, 2));
        float mn0 = fmaxf(m0, ml0), mn1 = fmaxf(m1, ml1);
        float al0 = __expf(m0 - mn0), al1 = __expf(m1 - mn1);
        float ll0 = 0.f, ll1 = 0.f;
        #pragma unroll
        for (int nf = 0; nf < 8; nf++) {
            sc[nf][0] = __expf(sc[nf][0] - mn0); ll0 += sc[nf][0];
            sc[nf][1] = __expf(sc[nf][1] - mn0); ll0 += sc[nf][1];
            sc[nf][2] = __expf(sc[nf][2] - mn1); ll1 += sc[nf][2];
            sc[nf][3] = __expf(sc[nf][3] - mn1); ll1 += sc[nf][3];
        }
        ll0 += __shfl_xor_sync(0xffffffffu, ll0, 1);
        ll0 += __shfl_xor_sync(0xffffffffu, ll0, 2);
        ll1 += __shfl_xor_sync(0xffffffffu, ll1, 1);
        ll1 += __shfl_xor_sync(0xffffffffu, ll1, 2);
        l0 = l0 * al0 + ll0; m0 = mn0;
        l1 = l1 * al1 + ll1; m1 = mn1;

        #pragma unroll
        for (int nt = 0; nt < 4; nt++) {
            ot[nt][0] *= al0; ot[nt][1] *= al0;
            ot[nt][2] *= al1; ot[nt][3] *= al1;
        }

        #pragma unroll
        for (int kc = 0; kc < 4; kc++) {
            unsigned pa[4];
            __half2 h0 = __floats2half2_rn(sc[2*kc][0],   sc[2*kc][1]);
            __half2 h1 = __floats2half2_rn(sc[2*kc][2],   sc[2*kc][3]);
            __half2 h2 = __floats2half2_rn(sc[2*kc+1][0], sc[2*kc+1][1]);
            __half2 h3 = __floats2half2_rn(sc[2*kc+1][2], sc[2*kc+1][3]);
            pa[0] = *(unsigned*)&h0; pa[1] = *(unsigned*)&h1;
            pa[2] = *(unsigned*)&h2; pa[3] = *(unsigned*)&h3;
            #pragma unroll
            for (int nt = 0; nt < 4; nt++) {
                unsigned b0 = *(const unsigned*)&Vts[nt*8 + g][kc*16 + 2*tg    ];
                unsigned b1 = *(const unsigned*)&Vts[nt*8 + g][kc*16 + 8 + 2*tg];
                mma_f16(ot[nt], pa, b0, b1);
            }
        }
        __syncthreads();
    }

    float inv0 = 1.f / l0, inv1 = 1.f / l1;
    float* ob = attn + ((size_t)b * 2048) * 512 + h*32;
    #pragma unroll
    for (int nt = 0; nt < 4; nt++) {
        *(float2*)(ob + (size_t)r0*512     + nt*8 + 2*tg) = make_float2(ot[nt][0]*inv0, ot[nt][1]*inv0);
        *(float2*)(ob + (size_t)(r0+8)*512 + nt*8 + 2*tg) = make_float2(ot[nt][2]*inv1, ot[nt][3]*inv1);
    }
}

// ---------------- launcher ----------------
extern "C" void kernel_launch(void* const* d_in, const int* in_sizes, int n_in,
                              void* d_out, int out_size)
{
    const float* x       = (const float*)d_in[0];
    const float* w_q     = (const float*)d_in[1];
    const float* w_k     = (const float*)d_in[2];
    const float* w_v     = (const float*)d_in[3];
    const float* g_lat   = (const float*)d_in[4];
    const float* g_kv    = (const float*)d_in[5];
    const float* cqw     = (const float*)d_in[6];
    const float* ckw     = (const float*)d_in[7];
    const float* gconv   = (const float*)d_in[8];
    const float* gkconv  = (const float*)d_in[9];
    const float* gpostq  = (const float*)d_in[10];
    const float* gpostk  = (const float*)d_in[11];
    const float* ktemp   = (const float*)d_in[12];
    const float* gpreout = (const float*)d_in[13];
    const float* w_o     = (const float*)d_in[14];
    float* out = (float*)d_out;

    float *qpre, *kpre, *vbuf, *qf, *kf, *vf, *attn;
    cudaGetSymbolAddress((void**)&qpre, g_qpre);
    cudaGetSymbolAddress((void**)&kpre, g_kpre);
    cudaGetSymbolAddress((void**)&vbuf, g_vbuf);
    cudaGetSymbolAddress((void**)&qf,   g_qf);
    cudaGetSymbolAddress((void**)&kf,   g_kf);
    cudaGetSymbolAddress((void**)&vf,   g_vf);
    cudaGetSymbolAddress((void**)&attn, g_attn);

    const int M = NB * SEQ;  // 8192

    // QKV projections (pipelined tf32 tensor cores)
    gemm_tf32<<<dim3(LATD/128, M/128), 256>>>(x, w_q, qpre, M, LATD, DIMM);
    gemm_tf32<<<dim3(KVDD/128, M/128), 256>>>(x, w_k, kpre, M, KVDD, DIMM);
    gemm_tf32<<<dim3(KVDD/128, M/128), 256>>>(x, w_v, vbuf, M, KVDD, DIMM);

    // fused first RMS norms (q, k, v)
    rms3_kernel<<<M, 128>>>(qpre, kpre, vbuf, g_lat, g_kv);

    // fused conv / mix / post-rms / head-norm / rope / relayout (8 tokens/block)
    mid_kernel<<<M/TOK, 128>>>(qpre, kpre, vbuf, cqw, ckw, gconv, gkconv,
                               gpostq, gpostk, ktemp, qf, kf, vf);

    // causal GQA attention (tensor cores)
    attn_mma_kernel<<<dim3(NB*NHH, SEQ/64), 128>>>(qf, kf, vf, attn);

    // pre-output RMS + output projection
    rms_kernel<<<M, 128>>>(attn, gpreout, LATD);
    gemm_tf32<<<dim3(DIMM/128, M/128), 256>>>(attn, w_o, out, M, DIMM, LATD);
}

// round 9
// speedup vs baseline: 5.0627x; 1.1107x over previous
#include <cuda_runtime.h>
#include <cuda_fp16.h>
#include <math.h>

#define NB   4
#define SEQ  2048
#define DIMM 2048
#define LATD 512
#define KVDD 128
#define NHH  16
#define NKVV 4
#define HDD  32
#define TOK  8

// ---------------- scratch (device globals; no allocations allowed) ----------------
__device__ float g_qpre[NB*SEQ*LATD];     // q after proj  [B,S,512]  (pre-RMS)
__device__ float g_kpre[NB*SEQ*KVDD];     // k after proj  [B,S,128]  (pre-RMS)
__device__ float g_vbuf[NB*SEQ*KVDD];     // v after proj  [B,S,128]  (pre-RMS)
__device__ float g_qf  [NB*NHH*SEQ*HDD];  // final q [B,16,S,32]
__device__ float g_kf  [NB*NKVV*SEQ*HDD]; // final k [B,4,S,32]
__device__ float g_vf  [NB*NKVV*SEQ*HDD]; // final v [B,4,S,32]
__device__ float g_attn[NB*SEQ*LATD];     // attention out [B,S,512]

__device__ __forceinline__ float f2tf32f(float f) {
    unsigned u; asm("cvt.rna.tf32.f32 %0, %1;" : "=r"(u) : "f"(f));
    return __uint_as_float(u);
}
__device__ __forceinline__ unsigned f2tf32u(float f) {
    unsigned u; asm("cvt.rna.tf32.f32 %0, %1;" : "=r"(u) : "f"(f));
    return u;
}

// ---------------- mma helpers ----------------
__device__ __forceinline__ void mma_tf32(float* c, const unsigned* a, unsigned b0, unsigned b1) {
    asm volatile(
        "mma.sync.aligned.m16n8k8.row.col.f32.tf32.tf32.f32 "
        "{%0,%1,%2,%3},{%4,%5,%6,%7},{%8,%9},{%0,%1,%2,%3};"
        : "+f"(c[0]), "+f"(c[1]), "+f"(c[2]), "+f"(c[3])
        : "r"(a[0]), "r"(a[1]), "r"(a[2]), "r"(a[3]), "r"(b0), "r"(b1));
}
__device__ __forceinline__ void mma_f16(float* c, const unsigned* a, unsigned b0, unsigned b1) {
    asm volatile(
        "mma.sync.aligned.m16n8k16.row.col.f32.f16.f16.f32 "
        "{%0,%1,%2,%3},{%4,%5,%6,%7},{%8,%9},{%0,%1,%2,%3};"
        : "+f"(c[0]), "+f"(c[1]), "+f"(c[2]), "+f"(c[3])
        : "r"(a[0]), "r"(a[1]), "r"(a[2]), "r"(a[3]), "r"(b0), "r"(b1));
}
__device__ __forceinline__ void cp16(unsigned smem_addr, const float* gptr) {
    asm volatile("cp.async.ca.shared.global [%0], [%1], 16;" :: "r"(smem_addr), "l"(gptr));
}

// ---------------- 3-stage pipelined 128x128 tf32 GEMM body ----------------
// Arow = A + brow*K, Brow = B + bn0*K, Cout = C + brow*Nout + ccol.
// 256 threads, BK=16, smem [m][k] stride 20 (16B-aligned rows, conflict-free frags).
__device__ __forceinline__ void gemm128_body(
    const float* __restrict__ Arow, const float* __restrict__ Brow,
    float* __restrict__ Cout, int Nout, int K)
{
    __shared__ float As[3][128*20];
    __shared__ float Bs[3][128*20];

    const int tid  = threadIdx.x;
    const int warp = tid >> 5, lane = tid & 31;
    const int g = lane >> 2, tg = lane & 3;
    const int wm = (warp >> 2) * 64;
    const int wn = (warp & 3) * 32;

    const int lr = tid >> 2;             // 0..63
    const int cq = (tid & 3) * 4;        // 0,4,8,12
    const float* Ag0 = Arow + (size_t)lr * K + cq;
    const float* Ag1 = Arow + (size_t)(lr + 64) * K + cq;
    const float* Bg0 = Brow + (size_t)lr * K + cq;
    const float* Bg1 = Brow + (size_t)(lr + 64) * K + cq;
    const int so0 = lr * 20 + cq;
    const int so1 = (lr + 64) * 20 + cq;

    unsigned sA0[3], sA1[3], sB0[3], sB1[3];
    #pragma unroll
    for (int st = 0; st < 3; st++) {
        sA0[st] = (unsigned)__cvta_generic_to_shared(&As[st][so0]);
        sA1[st] = (unsigned)__cvta_generic_to_shared(&As[st][so1]);
        sB0[st] = (unsigned)__cvta_generic_to_shared(&Bs[st][so0]);
        sB1[st] = (unsigned)__cvta_generic_to_shared(&Bs[st][so1]);
    }

    float acc[4][4][4];
    #pragma unroll
    for (int i = 0; i < 4; i++)
        #pragma unroll
        for (int j = 0; j < 4; j++)
            #pragma unroll
            for (int t = 0; t < 4; t++) acc[i][j][t] = 0.f;

    const int nk = K >> 4;

    // prologue: tiles 0,1 -> stages 0,1
    cp16(sA0[0], Ag0); cp16(sA1[0], Ag1); cp16(sB0[0], Bg0); cp16(sB1[0], Bg1);
    asm volatile("cp.async.commit_group;");
    cp16(sA0[1], Ag0 + 16); cp16(sA1[1], Ag1 + 16); cp16(sB0[1], Bg0 + 16); cp16(sB1[1], Bg1 + 16);
    asm volatile("cp.async.commit_group;");

    for (int t = 0; t < nk; t++) {
        const int cur = t % 3;
        if (t + 2 < nk) {
            const int nxt = (t + 2) % 3;
            const int k0 = (t + 2) << 4;
            cp16(sA0[nxt], Ag0 + k0); cp16(sA1[nxt], Ag1 + k0);
            cp16(sB0[nxt], Bg0 + k0); cp16(sB1[nxt], Bg1 + k0);
        }
        asm volatile("cp.async.commit_group;");
        asm volatile("cp.async.wait_group 2;");
        __syncthreads();

        const float* as = As[cur];
        const float* bs = Bs[cur];
        #pragma unroll
        for (int ks = 0; ks < 2; ks++) {
            const int kb = ks * 8;
            unsigned af[4][4], bf[4][2];
            #pragma unroll
            for (int mf = 0; mf < 4; mf++) {
                int r0 = wm + mf*16 + g;
                af[mf][0] = f2tf32u(as[r0*20     + kb + tg    ]);
                af[mf][1] = f2tf32u(as[(r0+8)*20 + kb + tg    ]);
                af[mf][2] = f2tf32u(as[r0*20     + kb + tg + 4]);
                af[mf][3] = f2tf32u(as[(r0+8)*20 + kb + tg + 4]);
            }
            #pragma unroll
            for (int nf = 0; nf < 4; nf++) {
                int cn = wn + nf*8 + g;
                bf[nf][0] = f2tf32u(bs[cn*20 + kb + tg    ]);
                bf[nf][1] = f2tf32u(bs[cn*20 + kb + tg + 4]);
            }
            #pragma unroll
            for (int mf = 0; mf < 4; mf++)
                #pragma unroll
                for (int nf = 0; nf < 4; nf++)
                    mma_tf32(acc[mf][nf], af[mf], bf[nf][0], bf[nf][1]);
        }
        __syncthreads();
    }

    #pragma unroll
    for (int mf = 0; mf < 4; mf++) {
        int r = wm + mf*16 + g;
        #pragma unroll
        for (int nf = 0; nf < 4; nf++) {
            int cn = wn + nf*8 + tg*2;
            *(float2*)(Cout + (size_t)r * Nout + cn)     = make_float2(acc[mf][nf][0], acc[mf][nf][1]);
            *(float2*)(Cout + (size_t)(r+8) * Nout + cn) = make_float2(acc[mf][nf][2], acc[mf][nf][3]);
        }
    }
}

// ---------------- fused QKV projection: one launch, full chip ----------------
// grid (6, 64): bx 0..3 -> q col-block bx; bx 4 -> k; bx 5 -> v.
__global__ __launch_bounds__(256) void gemm_qkv(
    const float* __restrict__ x,
    const float* __restrict__ wq, const float* __restrict__ wk, const float* __restrict__ wv,
    float* __restrict__ q, float* __restrict__ k, float* __restrict__ v)
{
    const int bx = blockIdx.x;
    const int brow = blockIdx.y * 128;
    const float* Bsel; float* Csel; int Nout, ccol;
    if (bx < 4)      { Bsel = wq + (size_t)bx*128*DIMM; Csel = q; Nout = 512; ccol = bx*128; }
    else if (bx == 4){ Bsel = wk;                        Csel = k; Nout = 128; ccol = 0; }
    else             { Bsel = wv;                        Csel = v; Nout = 128; ccol = 0; }
    gemm128_body(x + (size_t)brow*DIMM, Bsel, Csel + (size_t)brow*Nout + ccol, Nout, DIMM);
}

// ---------------- generic GEMM: C[M,N] = A[M,K] @ B[N,K]^T ----------------
__global__ __launch_bounds__(256) void gemm_tf32(
    const float* __restrict__ A, const float* __restrict__ B, float* __restrict__ C,
    int M, int N, int K)
{
    const int brow = blockIdx.y * 128;
    const int bcol = blockIdx.x * 128;
    gemm128_body(A + (size_t)brow*K, B + (size_t)bcol*K, C + (size_t)brow*N + bcol, N, K);
}

// ---------------- RMS helpers ----------------
__device__ __forceinline__ void rms_row_dev(float* p, const float* g, int C, int tid, float* red)
{
    float ss = 0.f;
    for (int i = tid; i < C; i += 128) { float v = p[i]; ss = fmaf(v, v, ss); }
    #pragma unroll
    for (int o = 16; o; o >>= 1) ss += __shfl_xor_sync(0xffffffffu, ss, o);
    if ((tid & 31) == 0) red[tid >> 5] = ss;
    __syncthreads();
    ss = red[0] + red[1] + red[2] + red[3];
    float r = rsqrtf(ss / C + 1e-6f);
    for (int i = tid; i < C; i += 128) p[i] = p[i] * r * g[i];
    __syncthreads();
}

__global__ __launch_bounds__(128) void rms_kernel(
    float* __restrict__ buf, const float* __restrict__ g, int C)
{
    __shared__ float red[4];
    size_t row = blockIdx.x;
    float* p = buf + row * C;
    int tid = threadIdx.x;
    float ss = 0.f;
    for (int i = tid; i < C; i += 128) { float v = p[i]; ss = fmaf(v, v, ss); }
    #pragma unroll
    for (int o = 16; o; o >>= 1) ss += __shfl_xor_sync(0xffffffffu, ss, o);
    if ((tid & 31) == 0) red[tid >> 5] = ss;
    __syncthreads();
    ss = red[0] + red[1] + red[2] + red[3];
    float r = rsqrtf(ss / C + 1e-6f);
    for (int i = tid; i < C; i += 128) p[i] = p[i] * r * g[i];
}

// ---------------- fused middle: first-RMS + conv + mix + post-rms + head-norm + rope ----------------
// 8 tokens per block; first RMS (q/k/v) fused here (halo rows normalized locally in smem).
__global__ __launch_bounds__(128) void mid_kernel(
    const float* __restrict__ qpre, const float* __restrict__ kpre, const float* __restrict__ vbuf,
    const float* __restrict__ gl,   const float* __restrict__ gkv,
    const float* __restrict__ cqw,  const float* __restrict__ ckw,
    const float* __restrict__ gconv, const float* __restrict__ gkconv,
    const float* __restrict__ gpostq, const float* __restrict__ gpostk,
    const float* __restrict__ ktemp,
    float* __restrict__ qf, float* __restrict__ kf, float* __restrict__ vf)
{
    int blk = blockIdx.x;                 // 1024 blocks
    int b   = blk >> 8;
    int s0  = (blk & 255) * TOK;
    int tid = threadIdx.x;

    __shared__ float sq[TOK+2][512];
    __shared__ float sk[TOK+2][128];
    __shared__ float sv[TOK][128];
    __shared__ float qc[TOK][512];
    __shared__ float kcs[TOK][128];
    __shared__ float qm[TOK][32], km[TOK][32];
    __shared__ float red[4];
    __shared__ float sclq[16], sclk[4];
    __shared__ float s_rq, s_rk, s_r2q, s_r2k;

    // load TOK+2 causal rows, apply first RMS in smem (same-thread load->reduce indexing)
    for (int t = 0; t < TOK+2; t++) {
        int srow = s0 - 2 + t;
        if (srow >= 0) {
            const float* srcq = qpre + ((size_t)b * 2048 + srow) * 512;
            for (int i = tid; i < 512; i += 128) sq[t][i] = srcq[i];
            sk[t][tid] = kpre[((size_t)b * 2048 + srow) * 128 + tid];
            rms_row_dev(sq[t], gl,  512, tid, red);
            rms_row_dev(sk[t], gkv, 128, tid, red);
        } else {
            for (int i = tid; i < 512; i += 128) sq[t][i] = 0.f;
            sk[t][tid] = 0.f;
            __syncthreads();
        }
    }
    // v rows: load + first RMS
    for (int t = 0; t < TOK; t++) {
        sv[t][tid] = vbuf[((size_t)b * 2048 + s0 + t) * 128 + tid];
        rms_row_dev(sv[t], gkv, 128, tid, red);
    }
    __syncthreads();

    // q conv: each thread 4 channels x 8 tokens; weights loaded once per block
    for (int c = tid; c < 512; c += 128) {
        int gb = (c >> 5) << 5;
        const float* w = cqw + c * 96;
        float a[TOK];
        #pragma unroll
        for (int t = 0; t < TOK; t++) a[t] = 0.f;
        for (int i = 0; i < 32; i++) {
            int ch = gb + i;
            float w0 = w[i*3], w1 = w[i*3+1], w2 = w[i*3+2];
            float r[TOK+2];
            #pragma unroll
            for (int t = 0; t < TOK+2; t++) r[t] = sq[t][ch];
            #pragma unroll
            for (int t = 0; t < TOK; t++)
                a[t] = fmaf(w0, r[t], fmaf(w1, r[t+1], fmaf(w2, r[t+2], a[t])));
        }
        #pragma unroll
        for (int t = 0; t < TOK; t++) qc[t][c] = a[t];
    }
    // k conv
    {
        int c = tid, gb = (c >> 5) << 5;
        const float* w = ckw + c * 96;
        float a[TOK];
        #pragma unroll
        for (int t = 0; t < TOK; t++) a[t] = 0.f;
        for (int i = 0; i < 32; i++) {
            int ch = gb + i;
            float w0 = w[i*3], w1 = w[i*3+1], w2 = w[i*3+2];
            float r[TOK+2];
            #pragma unroll
            for (int t = 0; t < TOK+2; t++) r[t] = sk[t][ch];
            #pragma unroll
            for (int t = 0; t < TOK; t++)
                a[t] = fmaf(w0, r[t], fmaf(w1, r[t+1], fmaf(w2, r[t+2], a[t])));
        }
        #pragma unroll
        for (int t = 0; t < TOK; t++) kcs[t][c] = a[t];
    }
    // head means of the pre-conv (post first-RMS) tensors
    for (int p = tid; p < TOK*32; p += 128) {
        int t = p >> 5, d = p & 31;
        float a = 0.f;
        #pragma unroll
        for (int h = 0; h < 16; h++) a += sq[t+2][h*32 + d];
        qm[t][d] = a * (1.0f/16.0f);
        float bb = 0.f;
        #pragma unroll
        for (int g2 = 0; g2 < 4; g2++) bb += sk[t+2][g2*32 + d];
        km[t][d] = bb * 0.25f;
    }
    __syncthreads();

    const float kt0 = ktemp[0];

    for (int t = 0; t < TOK; t++) {
        int s = s0 + t;
        float* qcv = qc[t];
        float* kcv = kcs[t];

        // rms over conv outputs
        float pq = 0.f;
        for (int i = tid; i < 512; i += 128) pq = fmaf(qcv[i], qcv[i], pq);
        float pk = kcv[tid] * kcv[tid];
        #pragma unroll
        for (int o = 16; o; o >>= 1) pq += __shfl_xor_sync(0xffffffffu, pq, o);
        if ((tid & 31) == 0) red[tid >> 5] = pq;
        __syncthreads();
        if (tid == 0) s_rq = rsqrtf((red[0]+red[1]+red[2]+red[3]) * (1.f/512.f) + 1e-6f);
        __syncthreads();
        #pragma unroll
        for (int o = 16; o; o >>= 1) pk += __shfl_xor_sync(0xffffffffu, pk, o);
        if ((tid & 31) == 0) red[tid >> 5] = pk;
        __syncthreads();
        if (tid == 0) s_rk = rsqrtf((red[0]+red[1]+red[2]+red[3]) * (1.f/128.f) + 1e-6f);
        __syncthreads();
        float rq = s_rq, rk = s_rk;

        // rms gains + cross-mix (GAIN=0.25)
        for (int i = tid; i < 512; i += 128) qcv[i] = qcv[i] * rq * gconv[i]  + 0.25f * km[t][i & 31];
        kcv[tid] = kcv[tid] * rk * gkconv[tid] + 0.25f * qm[t][tid & 31];
        __syncthreads();

        // post-rms
        float p2q = 0.f;
        for (int i = tid; i < 512; i += 128) p2q = fmaf(qcv[i], qcv[i], p2q);
        float p2k = kcv[tid] * kcv[tid];
        #pragma unroll
        for (int o = 16; o; o >>= 1) p2q += __shfl_xor_sync(0xffffffffu, p2q, o);
        if ((tid & 31) == 0) red[tid >> 5] = p2q;
        __syncthreads();
        if (tid == 0) s_r2q = rsqrtf((red[0]+red[1]+red[2]+red[3]) * (1.f/512.f) + 1e-6f);
        __syncthreads();
        #pragma unroll
        for (int o = 16; o; o >>= 1) p2k += __shfl_xor_sync(0xffffffffu, p2k, o);
        if ((tid & 31) == 0) red[tid >> 5] = p2k;
        __syncthreads();
        if (tid == 0) s_r2k = rsqrtf((red[0]+red[1]+red[2]+red[3]) * (1.f/128.f) + 1e-6f);
        __syncthreads();
        float r2q = s_r2q, r2k = s_r2k;
        for (int i = tid; i < 512; i += 128) qcv[i] = qcv[i] * r2q * gpostq[i];
        kcv[tid] = kcv[tid] * r2k * gpostk[tid];
        __syncthreads();

        // per-head L2 norm -> scale to sqrt(HD) (k also * key_temp)
        if (tid < 16) {
            float a = 0.f;
            #pragma unroll
            for (int d = 0; d < 32; d++) { float v = qcv[tid*32 + d]; a = fmaf(v, v, a); }
            sclq[tid] = 5.656854249492381f / fmaxf(sqrtf(a), 1e-12f);
        }
        if (tid >= 16 && tid < 20) {
            int g2 = tid - 16; float a = 0.f;
            #pragma unroll
            for (int d = 0; d < 32; d++) { float v = kcv[g2*32 + d]; a = fmaf(v, v, a); }
            sclk[g2] = 5.656854249492381f * kt0 / fmaxf(sqrtf(a), 1e-12f);
        }
        __syncthreads();

        // rope + relayout
        for (int p = tid; p < 256; p += 128) {
            int h = p >> 4, d2 = p & 15;
            float fr = powf(10000.f, -(float)d2 * (1.f/16.f));
            float ang = (float)s * fr;
            float sn, cs; sincosf(ang, &sn, &cs);
            float scl = sclq[h];
            float x0 = qcv[h*32 + 2*d2]     * scl;
            float x1 = qcv[h*32 + 2*d2 + 1] * scl;
            float* dst = qf + (((size_t)(b*16 + h)) * 2048 + s) * 32 + 2*d2;
            dst[0] = x0*cs - x1*sn;
            dst[1] = x0*sn + x1*cs;
        }
        if (tid < 64) {
            int g2 = tid >> 4, d2 = tid & 15;
            float fr = powf(10000.f, -(float)d2 * (1.f/16.f));
            float ang = (float)s * fr;
            float sn, cs; sincosf(ang, &sn, &cs);
            float scl = sclk[g2];
            float x0 = kcv[g2*32 + 2*d2]     * scl;
            float x1 = kcv[g2*32 + 2*d2 + 1] * scl;
            float* dst = kf + (((size_t)(b*4 + g2)) * 2048 + s) * 32 + 2*d2;
            dst[0] = x0*cs - x1*sn;
            dst[1] = x0*sn + x1*cs;
        }
        {
            float vv = sv[t][tid];
            int g2 = tid >> 5, d = tid & 31;
            vf[(((size_t)(b*4 + g2)) * 2048 + s) * 32 + d] = vv;
        }
        __syncthreads();
    }
}

// ---------------- tensor-core flash attention (causal, GQA) ----------------
// qt reversed vs blockIdx.y so the longest (most-tiles) blocks are scheduled first.
__global__ __launch_bounds__(128, 4) void attn_mma_kernel(
    const float* __restrict__ qf, const float* __restrict__ kf, const float* __restrict__ vf,
    float* __restrict__ attn)
{
    const int bh = blockIdx.x;            // b*16 + h
    const int qt = (int)gridDim.y - 1 - (int)blockIdx.y;   // LPT scheduling
    const int b = bh >> 4, h = bh & 15;
    const int kvh = h >> 2;
    const int tid = threadIdx.x;
    const int w = tid >> 5, lane = tid & 31;
    const int g = lane >> 2, tg = lane & 3;

    __shared__ float  Ks[64][40];
    __shared__ __half Vts[32][72];

    const float scale = 0.17677669529663687f;
    const int r0 = qt*64 + w*16 + g;

    unsigned qa[4][4];
    {
        const float* qb = qf + ((size_t)bh * 2048) * 32;
        #pragma unroll
        for (int ch = 0; ch < 4; ch++) {
            qa[ch][0] = f2tf32u(qb[(size_t)r0*32     + ch*8 + tg    ] * scale);
            qa[ch][1] = f2tf32u(qb[(size_t)(r0+8)*32 + ch*8 + tg    ] * scale);
            qa[ch][2] = f2tf32u(qb[(size_t)r0*32     + ch*8 + tg + 4] * scale);
            qa[ch][3] = f2tf32u(qb[(size_t)(r0+8)*32 + ch*8 + tg + 4] * scale);
        }
    }

    float m0 = -3.0e38f, m1 = -3.0e38f, l0 = 0.f, l1 = 0.f;
    float ot[4][4];
    #pragma unroll
    for (int nt = 0; nt < 4; nt++)
        #pragma unroll
        for (int t = 0; t < 4; t++) ot[nt][t] = 0.f;

    const float* kbase = kf + (size_t)(b*4 + kvh) * 2048 * 32;
    const float* vbase = vf + (size_t)(b*4 + kvh) * 2048 * 32;

    for (int j = 0; j <= qt; j++) {
        #pragma unroll
        for (int i = 0; i < 4; i++) {
            int idx = tid + i*128;
            int row = idx >> 3, dq = (idx & 7) * 4;
            float4 kv = *(const float4*)(kbase + (size_t)(j*64 + row)*32 + dq);
            float4 kt;
            kt.x = f2tf32f(kv.x); kt.y = f2tf32f(kv.y);
            kt.z = f2tf32f(kv.z); kt.w = f2tf32f(kv.w);
            *(float4*)&Ks[row][dq] = kt;
        }
        #pragma unroll
        for (int i = 0; i < 2; i++) {
            int idx = tid + i*128;
            int c = idx >> 5, pr = idx & 31;
            const float* vp = vbase + (size_t)(j*64 + 2*pr)*32 + 4*c;
            float4 v0 = *(const float4*)vp;
            float4 v1 = *(const float4*)(vp + 32);
            *(__half2*)&Vts[4*c+0][2*pr] = __floats2half2_rn(v0.x, v1.x);
            *(__half2*)&Vts[4*c+1][2*pr] = __floats2half2_rn(v0.y, v1.y);
            *(__half2*)&Vts[4*c+2][2*pr] = __floats2half2_rn(v0.z, v1.z);
            *(__half2*)&Vts[4*c+3][2*pr] = __floats2half2_rn(v0.w, v1.w);
        }
        __syncthreads();

        float sc[8][4];
        #pragma unroll
        for (int nf = 0; nf < 8; nf++)
            #pragma unroll
            for (int t = 0; t < 4; t++) sc[nf][t] = 0.f;
        #pragma unroll
        for (int ch = 0; ch < 4; ch++) {
            #pragma unroll
            for (int nf = 0; nf < 8; nf++) {
                unsigned b0 = __float_as_uint(Ks[nf*8 + g][ch*8 + tg    ]);
                unsigned b1 = __float_as_uint(Ks[nf*8 + g][ch*8 + tg + 4]);
                mma_tf32(sc[nf], qa[ch], b0, b1);
            }
        }

        if (j == qt) {
            int cb = qt*64;
            #pragma unroll
            for (int nf = 0; nf < 8; nf++) {
                #pragma unroll
                for (int bb = 0; bb < 2; bb++) {
                    int col = cb + nf*8 + 2*tg + bb;
                    if (col > r0)     sc[nf][bb]     = -1.0e30f;
                    if (col > r0 + 8) sc[nf][2 + bb] = -1.0e30f;
                }
            }
        }

        float ml0 = -1.0e30f, ml1 = -1.0e30f;
        #pragma unroll
        for (int nf = 0; nf < 8; nf++) {
            ml0 = fmaxf(ml0, fmaxf(sc[nf][0], sc[nf][1]));
            ml1 = fmaxf(ml1, fmaxf(sc[nf][2], sc[nf][3]));
        }
        ml0 = fmaxf(ml0, __shfl_xor_sync(0xffffffffu, ml0, 1));
        ml0 = fmaxf(ml0, __shfl_xor_sync(0xffffffffu, ml0, 2));
        ml1 = fmaxf(ml1, __shfl_xor_sync(0xffffffffu, ml1, 1));
        ml1 = fmaxf(ml1, __shfl_xor_sync(0xffffffffu, ml1, 2));
        float mn0 = fmaxf(m0, ml0), mn1 = fmaxf(m1, ml1);
        float al0 = __expf(m0 - mn0), al1 = __expf(m1 - mn1);
        float ll0 = 0.f, ll1 = 0.f;
        #pragma unroll
        for (int nf = 0; nf < 8; nf++) {
            sc[nf][0] = __expf(sc[nf][0] - mn0); ll0 += sc[nf][0];
            sc[nf][1] = __expf(sc[nf][1] - mn0); ll0 += sc[nf][1];
            sc[nf][2] = __expf(sc[nf][2] - mn1); ll1 += sc[nf][2];
            sc[nf][3] = __expf(sc[nf][3] - mn1); ll1 += sc[nf][3];
        }
        ll0 += __shfl_xor_sync(0xffffffffu, ll0, 1);
        ll0 += __shfl_xor_sync(0xffffffffu, ll0, 2);
        ll1 += __shfl_xor_sync(0xffffffffu, ll1, 1);
        ll1 += __shfl_xor_sync(0xffffffffu, ll1, 2);
        l0 = l0 * al0 + ll0; m0 = mn0;
        l1 = l1 * al1 + ll1; m1 = mn1;

        #pragma unroll
        for (int nt = 0; nt < 4; nt++) {
            ot[nt][0] *= al0; ot[nt][1] *= al0;
            ot[nt][2] *= al1; ot[nt][3] *= al1;
        }

        #pragma unroll
        for (int kc = 0; kc < 4; kc++) {
            unsigned pa[4];
            __half2 h0 = __floats2half2_rn(sc[2*kc][0],   sc[2*kc][1]);
            __half2 h1 = __floats2half2_rn(sc[2*kc][2],   sc[2*kc][3]);
            __half2 h2 = __floats2half2_rn(sc[2*kc+1][0], sc[2*kc+1][1]);
            __half2 h3 = __floats2half2_rn(sc[2*kc+1][2], sc[2*kc+1][3]);
            pa[0] = *(unsigned*)&h0; pa[1] = *(unsigned*)&h1;
            pa[2] = *(unsigned*)&h2; pa[3] = *(unsigned*)&h3;
            #pragma unroll
            for (int nt = 0; nt < 4; nt++) {
                unsigned b0 = *(const unsigned*)&Vts[nt*8 + g][kc*16 + 2*tg    ];
                unsigned b1 = *(const unsigned*)&Vts[nt*8 + g][kc*16 + 8 + 2*tg];
                mma_f16(ot[nt], pa, b0, b1);
            }
        }
        __syncthreads();
    }

    float inv0 = 1.f / l0, inv1 = 1.f / l1;
    float* ob = attn + ((size_t)b * 2048) * 512 + h*32;
    #pragma unroll
    for (int nt = 0; nt < 4; nt++) {
        *(float2*)(ob + (size_t)r0*512     + nt*8 + 2*tg) = make_float2(ot[nt][0]*inv0, ot[nt][1]*inv0);
        *(float2*)(ob + (size_t)(r0+8)*512 + nt*8 + 2*tg) = make_float2(ot[nt][2]*inv1, ot[nt][3]*inv1);
    }
}

// ---------------- launcher ----------------
extern "C" void kernel_launch(void* const* d_in, const int* in_sizes, int n_in,
                              void* d_out, int out_size)
{
    const float* x       = (const float*)d_in[0];
    const float* w_q     = (const float*)d_in[1];
    const float* w_k     = (const float*)d_in[2];
    const float* w_v     = (const float*)d_in[3];
    const float* g_lat   = (const float*)d_in[4];
    const float* g_kv    = (const float*)d_in[5];
    const float* cqw     = (const float*)d_in[6];
    const float* ckw     = (const float*)d_in[7];
    const float* gconv   = (const float*)d_in[8];
    const float* gkconv  = (const float*)d_in[9];
    const float* gpostq  = (const float*)d_in[10];
    const float* gpostk  = (const float*)d_in[11];
    const float* ktemp   = (const float*)d_in[12];
    const float* gpreout = (const float*)d_in[13];
    const float* w_o     = (const float*)d_in[14];
    float* out = (float*)d_out;

    float *qpre, *kpre, *vbuf, *qf, *kf, *vf, *attn;
    cudaGetSymbolAddress((void**)&qpre, g_qpre);
    cudaGetSymbolAddress((void**)&kpre, g_kpre);
    cudaGetSymbolAddress((void**)&vbuf, g_vbuf);
    cudaGetSymbolAddress((void**)&qf,   g_qf);
    cudaGetSymbolAddress((void**)&kf,   g_kf);
    cudaGetSymbolAddress((void**)&vf,   g_vf);
    cudaGetSymbolAddress((void**)&attn, g_attn);

    const int M = NB * SEQ;  // 8192

    // fused QKV projection (one launch, 384 CTAs)
    gemm_qkv<<<dim3(6, M/128), 256>>>(x, w_q, w_k, w_v, qpre, kpre, vbuf);

    // fused first-RMS + conv / mix / post-rms / head-norm / rope / relayout
    mid_kernel<<<M/TOK, 128>>>(qpre, kpre, vbuf, g_lat, g_kv, cqw, ckw, gconv, gkconv,
                               gpostq, gpostk, ktemp, qf, kf, vf);

    // causal GQA attention (tensor cores, LPT block order)
    attn_mma_kernel<<<dim3(NB*NHH, SEQ/64), 128>>>(qf, kf, vf, attn);

    // pre-output RMS + output projection
    rms_kernel<<<M, 128>>>(attn, gpreout, LATD);
    gemm_tf32<<<dim3(DIMM/128, M/128), 256>>>(attn, w_o, out, M, DIMM, LATD);
}